// round 13
// baseline (speedup 1.0000x reference)
#include <cuda_runtime.h>
#include <cuda_bf16.h>
#include <math.h>

#define COLS 8192   // B*N
#define NPTS 2048
#define NB 4
#define KNB 16

// ---------------- static device scratch ----------------
__device__ float g_xt[3*COLS];
__device__ unsigned short g_idx[COLS*KNB];
__device__ float g_P[512*COLS];
__device__ float g_Q[512*COLS];
__device__ float g_ymax[512*COLS];
__device__ float g_ypre[1024*COLS];
__device__ double g_dsum[4096];
__device__ double g_dsq[4096];
// pair-packed bf16 activations
__device__ unsigned g_TPH[8*COLS],   g_TPL[8*COLS];
__device__ unsigned g_XPH[384*COLS], g_XPL[384*COLS];
__device__ unsigned g_HPH[512*COLS], g_HPL[512*COLS];
// pair-packed bf16 weights
__device__ unsigned g_W1H[76288], g_W1L[76288], g_W2H[76288], g_W2L[76288];
__device__ unsigned g_WSH[434176], g_WSL[434176];
// tail buffers
__device__ float g_g[NB*2048];
__device__ float g_lat[NB*2048];
__device__ float g_x1v[NB*1024];
__device__ float g_x2v[NB*512];
__device__ float g_x3v[NB*256];
__device__ float g_pc1[NB*192];
__device__ float g_pc2f[NB*8192];
__device__ float g_pc2xyz[NB*384];
__device__ float g_pc3f[NB*65536];
__device__ float g_pc3tmp[NB*64*512];
__device__ float g_pc3xyz[NB*1536];

__device__ __forceinline__ const unsigned* xpH(int s){ return s==0? g_TPH : (s==1? g_XPH : g_HPH); }
__device__ __forceinline__ const unsigned* xpL(int s){ return s==0? g_TPL : (s==1? g_XPL : g_HPL); }
__device__ __forceinline__ float* buf_ptr(int s) {
    switch (s) {
        case 0: return g_g;    case 1: return g_lat;
        case 2: return g_x1v;  case 3: return g_x2v;
        case 4: return g_x3v;  case 5: return g_pc1;
        case 6: return g_pc2f; case 7: return g_pc3f;
    }
    return g_g;
}

// ---- helpers ----
__device__ __forceinline__ void split_bf16(float v, unsigned short &h, unsigned short &l){
    __nv_bfloat16 bh = __float2bfloat16_rn(v);
    float r = v - __bfloat162float(bh);
    __nv_bfloat16 bl = __float2bfloat16_rn(r);
    h = *(unsigned short*)&bh;
    l = *(unsigned short*)&bl;
}
__device__ __forceinline__ void split2(float a, float b, unsigned &h, unsigned &l){
    unsigned short ah,al,bh,bl;
    split_bf16(a, ah, al);
    split_bf16(b, bh, bl);
    h = (unsigned)ah | ((unsigned)bh << 16);
    l = (unsigned)al | ((unsigned)bl << 16);
}
__device__ __forceinline__ void mma16816(float* c, unsigned a0, unsigned a1, unsigned a2, unsigned a3,
                                         unsigned b0, unsigned b1){
    asm volatile(
        "mma.sync.aligned.m16n8k16.row.col.f32.bf16.bf16.f32 "
        "{%0,%1,%2,%3}, {%4,%5,%6,%7}, {%8,%9}, {%0,%1,%2,%3};"
        : "+f"(c[0]), "+f"(c[1]), "+f"(c[2]), "+f"(c[3])
        : "r"(a0), "r"(a1), "r"(a2), "r"(a3), "r"(b0), "r"(b1));
}
__device__ __forceinline__ unsigned smaddr(const void* p){
    return (unsigned)__cvta_generic_to_shared(p);
}
__device__ __forceinline__ void cp16(unsigned dst, const void* src){
    asm volatile("cp.async.ca.shared.global [%0], [%1], 16;" :: "r"(dst), "l"(src));
}

// ---------------- kernels ----------------

__global__ void k_zero(int O){
    int o = blockIdx.x*blockDim.x + threadIdx.x;
    if (o < O){ g_dsum[o]=0.0; g_dsq[o]=0.0; }
}

// fused transpose + xt bf16 pairs
__global__ void k_xt(const float* __restrict__ x) {
    int t = blockIdx.x*blockDim.x + threadIdx.x;
    if (t >= 8*COLS) return;
    int pr = t >> 13, col = t & 8191;
    int b = col >> 11, n = col & 2047;
    int c0 = 2*pr, c1 = 2*pr+1;
    float v0 = (c0 < 3) ? x[(b*NPTS+n)*3 + c0] : 0.f;
    float v1 = (c1 < 3) ? x[(b*NPTS+n)*3 + c1] : 0.f;
    if (c0 < 3) g_xt[c0*COLS + col] = v0;
    if (c1 < 3) g_xt[c1*COLS + col] = v1;
    unsigned h, l;
    split2(v0, v1, h, l);
    g_TPH[t] = h; g_TPL[t] = l;
}

__device__ __forceinline__ void wsplit_dual_elem(const float* W, int t, int woff, int K, int ldp){
    int o = t / ldp, kp = t - o*ldp;
    int kk = 2*kp;
    float w1a = 0.f, w1b = 0.f, w2a = 0.f, w2b = 0.f;
    if (kk < K){
        w1a = W[(size_t)o*2*K + kk];
        w2a = W[(size_t)o*2*K + K + kk] - w1a;
    }
    if (kk+1 < K){
        w1b = W[(size_t)o*2*K + kk+1];
        w2b = W[(size_t)o*2*K + K + kk+1] - w1b;
    }
    unsigned h, l;
    split2(w1a, w1b, h, l); g_W1H[woff+t] = h; g_W1L[woff+t] = l;
    split2(w2a, w2b, h, l); g_W2H[woff+t] = h; g_W2L[woff+t] = l;
}
__device__ __forceinline__ void wsplit_stats_elem(const float* W, int t, int woff, int K, int ldp){
    int o = t / ldp, kp = t - o*ldp;
    int kk = 2*kp;
    float wa = (kk   < K) ? W[(size_t)o*K + kk]   : 0.f;
    float wb = (kk+1 < K) ? W[(size_t)o*K + kk+1] : 0.f;
    unsigned h, l;
    split2(wa, wb, h, l); g_WSH[woff+t] = h; g_WSL[woff+t] = l;
}

// all 6 weight splits in one launch. segments (element counts):
// c2 dual 2048 | c3 dual 8192 | c4 dual 65536 | s21 8192 | s31 32768 | s5 393216
__global__ void k_wsplit_all(const float* __restrict__ w2, const float* __restrict__ w3,
                             const float* __restrict__ w4, const float* __restrict__ s21,
                             const float* __restrict__ s31, const float* __restrict__ s5){
    int t = blockIdx.x*blockDim.x + threadIdx.x;
    if (t < 2048){ wsplit_dual_elem(w2, t, 512, 64, 32); return; }
    t -= 2048;
    if (t < 8192){ wsplit_dual_elem(w3, t, 2560, 128, 64); return; }
    t -= 8192;
    if (t < 65536){ wsplit_dual_elem(w4, t, 10752, 256, 128); return; }
    t -= 65536;
    if (t < 8192){ wsplit_stats_elem(s21, t, 0, 128, 64); return; }
    t -= 8192;
    if (t < 32768){ wsplit_stats_elem(s31, t, 8192, 256, 128); return; }
    t -= 32768;
    if (t < 393216){ wsplit_stats_elem(s5, t, 40960, 768, 384); return; }
}

// KNN k=16
__global__ void k_knn() {   // grid (NB, 16), 128 threads
    __shared__ float sx[NPTS], sy[NPTS], sz[NPTS], sxx[NPTS];
    int b = blockIdx.x;
    for (int j = threadIdx.x; j < NPTS; j += blockDim.x) {
        float vx = g_xt[0*COLS + b*NPTS + j];
        float vy = g_xt[1*COLS + b*NPTS + j];
        float vz = g_xt[2*COLS + b*NPTS + j];
        sx[j]=vx; sy[j]=vy; sz[j]=vz; sxx[j]=vx*vx+vy*vy+vz*vz;
    }
    __syncthreads();
    int i = blockIdx.y*128 + threadIdx.x;
    float cx=sx[i], cy=sy[i], cz=sz[i], cxx=sxx[i];
    float pdk[KNB]; int idk[KNB];
    #pragma unroll
    for (int m=0;m<KNB;m++){ pdk[m]=-1e30f; idk[m]=0; }
    for (int j=0;j<NPTS;j++){
        float pd = 2.f*(cx*sx[j]+cy*sy[j]+cz*sz[j]) - cxx - sxx[j];
        if (pd > pdk[KNB-1]) {
            pdk[KNB-1]=pd; idk[KNB-1]=j;
            #pragma unroll
            for (int m=KNB-1;m>0;m--){
                bool sw = pdk[m] > pdk[m-1];
                float tp = sw ? pdk[m-1] : pdk[m];
                int   ti = sw ? idk[m-1] : idk[m];
                pdk[m-1] = sw ? pdk[m] : pdk[m-1];
                idk[m-1] = sw ? idk[m] : idk[m-1];
                pdk[m] = tp; idk[m] = ti;
            }
        }
    }
    #pragma unroll
    for (int m=0;m<KNB;m++)
        g_idx[(b*NPTS+i)*KNB+m] = (unsigned short)idk[m];
}

// ---- tensor-core GEMMs (unchanged hot loop) ----

__global__ void __launch_bounds__(256, 2)
k_gemm_dual(int xsel, int woff, int Kp, int ldp) {
    __shared__ unsigned sA1h[2][64][12], sA1l[2][64][12], sA2h[2][64][12], sA2l[2][64][12];
    __shared__ unsigned sBh[2][8][136], sBl[2][8][136];
    const unsigned* XH = xpH(xsel);
    const unsigned* XL = xpL(xsel);
    int tid = threadIdx.x;
    int warp = tid >> 5, lane = tid & 31;
    int mw = warp >> 1, nw = warp & 1;
    int gid = lane >> 2, qid = lane & 3;
    int o0 = blockIdx.y*64, n0 = blockIdx.x*128;
    int arow = (tid & 127) >> 1, ahalf = tid & 1;
    int bpr = tid >> 5, bc4 = tid & 31;
    bool hiA = (tid < 128);

    float accP[8][4], accQ[8][4];
    #pragma unroll
    for (int nt=0;nt<8;nt++)
        #pragma unroll
        for (int e=0;e<4;e++){ accP[nt][e]=0.f; accQ[nt][e]=0.f; }

    auto load_chunk = [&](int kp0, int buf){
        size_t aoff = (size_t)(woff + (o0 + arow)*ldp + kp0 + ahalf*4);
        unsigned adst = (arow*12 + ahalf*4)*4;
        if (hiA){
            cp16(smaddr(&sA1h[buf][0][0]) + adst, (const void*)(g_W1H + aoff));
            cp16(smaddr(&sA2h[buf][0][0]) + adst, (const void*)(g_W2H + aoff));
        } else {
            cp16(smaddr(&sA1l[buf][0][0]) + adst, (const void*)(g_W1L + aoff));
            cp16(smaddr(&sA2l[buf][0][0]) + adst, (const void*)(g_W2L + aoff));
        }
        size_t boff = (size_t)(kp0 + bpr)*COLS + n0 + bc4*4;
        unsigned bdst = (bpr*136 + bc4*4)*4;
        cp16(smaddr(&sBh[buf][0][0]) + bdst, (const void*)(XH + boff));
        cp16(smaddr(&sBl[buf][0][0]) + bdst, (const void*)(XL + boff));
    };

    int nch = Kp >> 4;
    load_chunk(0, 0);
    asm volatile("cp.async.commit_group;");
    for (int i = 0; i < nch; i++){
        int buf = i & 1;
        if (i + 1 < nch){
            load_chunk((i+1) << 3, (i+1) & 1);
            asm volatile("cp.async.commit_group;");
            asm volatile("cp.async.wait_group 1;");
        } else {
            asm volatile("cp.async.wait_group 0;");
        }
        __syncthreads();
        int rA = mw*16 + gid;
        unsigned a1h0=sA1h[buf][rA][qid], a1h1=sA1h[buf][rA+8][qid], a1h2=sA1h[buf][rA][qid+4], a1h3=sA1h[buf][rA+8][qid+4];
        unsigned a1l0=sA1l[buf][rA][qid], a1l1=sA1l[buf][rA+8][qid], a1l2=sA1l[buf][rA][qid+4], a1l3=sA1l[buf][rA+8][qid+4];
        unsigned a2h0=sA2h[buf][rA][qid], a2h1=sA2h[buf][rA+8][qid], a2h2=sA2h[buf][rA][qid+4], a2h3=sA2h[buf][rA+8][qid+4];
        unsigned a2l0=sA2l[buf][rA][qid], a2l1=sA2l[buf][rA+8][qid], a2l2=sA2l[buf][rA][qid+4], a2l3=sA2l[buf][rA+8][qid+4];
        #pragma unroll
        for (int nt=0;nt<8;nt++){
            int nc = nw*64 + nt*8 + gid;
            unsigned bh0 = sBh[buf][qid][nc], bh1 = sBh[buf][qid+4][nc];
            unsigned bl0 = sBl[buf][qid][nc], bl1 = sBl[buf][qid+4][nc];
            mma16816(accP[nt], a1h0,a1h1,a1h2,a1h3, bh0,bh1);
            mma16816(accP[nt], a1l0,a1l1,a1l2,a1l3, bh0,bh1);
            mma16816(accP[nt], a1h0,a1h1,a1h2,a1h3, bl0,bl1);
            mma16816(accQ[nt], a2h0,a2h1,a2h2,a2h3, bh0,bh1);
            mma16816(accQ[nt], a2l0,a2l1,a2l2,a2l3, bh0,bh1);
            mma16816(accQ[nt], a2h0,a2h1,a2h2,a2h3, bl0,bl1);
        }
        __syncthreads();
    }
    int r0 = o0 + mw*16 + gid, r1 = r0 + 8;
    #pragma unroll
    for (int nt=0;nt<8;nt++){
        int col = n0 + nw*64 + nt*8 + 2*qid;
        *(float2*)&g_P[(size_t)r0*COLS + col] = make_float2(accP[nt][0], accP[nt][1]);
        *(float2*)&g_P[(size_t)r1*COLS + col] = make_float2(accP[nt][2], accP[nt][3]);
        *(float2*)&g_Q[(size_t)r0*COLS + col] = make_float2(accQ[nt][0], accQ[nt][1]);
        *(float2*)&g_Q[(size_t)r1*COLS + col] = make_float2(accQ[nt][2], accQ[nt][3]);
    }
}

__global__ void __launch_bounds__(256, 2)
k_gemm_stats(int xsel, int woff, int Kp, int ldp, int soff) {
    __shared__ unsigned sAh[2][64][12], sAl[2][64][12];
    __shared__ unsigned sBh[2][8][136], sBl[2][8][136];
    __shared__ float sSum[64], sSq[64];
    const unsigned* XH = xpH(xsel);
    const unsigned* XL = xpL(xsel);
    int tid = threadIdx.x;
    int warp = tid >> 5, lane = tid & 31;
    int mw = warp >> 1, nw = warp & 1;
    int gid = lane >> 2, qid = lane & 3;
    int o0 = blockIdx.y*64, n0 = blockIdx.x*128;
    int arow = (tid & 127) >> 1, ahalf = tid & 1;
    int bpr = tid >> 5, bc4 = tid & 31;
    bool hiA = (tid < 128);

    float acc[8][4];
    #pragma unroll
    for (int nt=0;nt<8;nt++)
        #pragma unroll
        for (int e=0;e<4;e++) acc[nt][e]=0.f;

    auto load_chunk = [&](int kp0, int buf){
        size_t aoff = (size_t)(woff + (o0 + arow)*ldp + kp0 + ahalf*4);
        unsigned adst = (arow*12 + ahalf*4)*4;
        if (hiA) cp16(smaddr(&sAh[buf][0][0]) + adst, (const void*)(g_WSH + aoff));
        else     cp16(smaddr(&sAl[buf][0][0]) + adst, (const void*)(g_WSL + aoff));
        size_t boff = (size_t)(kp0 + bpr)*COLS + n0 + bc4*4;
        unsigned bdst = (bpr*136 + bc4*4)*4;
        cp16(smaddr(&sBh[buf][0][0]) + bdst, (const void*)(XH + boff));
        cp16(smaddr(&sBl[buf][0][0]) + bdst, (const void*)(XL + boff));
    };

    int nch = Kp >> 4;
    load_chunk(0, 0);
    asm volatile("cp.async.commit_group;");
    for (int i = 0; i < nch; i++){
        int buf = i & 1;
        if (i + 1 < nch){
            load_chunk((i+1) << 3, (i+1) & 1);
            asm volatile("cp.async.commit_group;");
            asm volatile("cp.async.wait_group 1;");
        } else {
            asm volatile("cp.async.wait_group 0;");
        }
        __syncthreads();
        int rA = mw*16 + gid;
        unsigned ah0=sAh[buf][rA][qid], ah1=sAh[buf][rA+8][qid], ah2=sAh[buf][rA][qid+4], ah3=sAh[buf][rA+8][qid+4];
        unsigned al0=sAl[buf][rA][qid], al1=sAl[buf][rA+8][qid], al2=sAl[buf][rA][qid+4], al3=sAl[buf][rA+8][qid+4];
        #pragma unroll
        for (int nt=0;nt<8;nt++){
            int nc = nw*64 + nt*8 + gid;
            unsigned bh0 = sBh[buf][qid][nc], bh1 = sBh[buf][qid+4][nc];
            unsigned bl0 = sBl[buf][qid][nc], bl1 = sBl[buf][qid+4][nc];
            mma16816(acc[nt], ah0,ah1,ah2,ah3, bh0,bh1);
            mma16816(acc[nt], al0,al1,al2,al3, bh0,bh1);
            mma16816(acc[nt], ah0,ah1,ah2,ah3, bl0,bl1);
        }
        __syncthreads();
    }
    if (tid < 64) { sSum[tid]=0.f; sSq[tid]=0.f; }
    __syncthreads();
    int lr0 = mw*16 + gid, lr1 = lr0 + 8;
    int r0 = o0 + lr0, r1 = o0 + lr1;
    float s0=0.f,q0=0.f,s1=0.f,q1=0.f;
    #pragma unroll
    for (int nt=0;nt<8;nt++){
        int col = n0 + nw*64 + nt*8 + 2*qid;
        float c0=acc[nt][0], c1=acc[nt][1], c2=acc[nt][2], c3=acc[nt][3];
        s0 += c0+c1; q0 += c0*c0+c1*c1;
        s1 += c2+c3; q1 += c2*c2+c3*c3;
        *(float2*)&g_ypre[(size_t)r0*COLS + col] = make_float2(c0, c1);
        *(float2*)&g_ypre[(size_t)r1*COLS + col] = make_float2(c2, c3);
    }
    atomicAdd(&sSum[lr0], s0); atomicAdd(&sSq[lr0], q0);
    atomicAdd(&sSum[lr1], s1); atomicAdd(&sSq[lr1], q1);
    __syncthreads();
    if (tid < 64) {
        atomicAdd(&g_dsum[soff+o0+tid], (double)sSum[tid]);
        atomicAdd(&g_dsq[soff+o0+tid],  (double)sSq[tid]);
    }
}

// conv1 fused gemm+gather (fp32 exact), stats at soff
__global__ void __launch_bounds__(256) k_gather1(const float* __restrict__ W, int soff){  // grid (32, NB)
    __shared__ float s0[NPTS], s1[NPTS], s2[NPTS];
    __shared__ float sP0[NPTS], sP1[NPTS];
    int op = blockIdx.x, b = blockIdx.y;
    int o0 = 2*op, o1 = o0 + 1;
    for (int j = threadIdx.x; j < NPTS; j += 256){
        s0[j] = g_xt[0*COLS + b*NPTS + j];
        s1[j] = g_xt[1*COLS + b*NPTS + j];
        s2[j] = g_xt[2*COLS + b*NPTS + j];
    }
    __syncthreads();
    float w10=W[o0*6], w11=W[o0*6+1], w12=W[o0*6+2];
    float v20=W[o0*6+3]-w10, v21=W[o0*6+4]-w11, v22=W[o0*6+5]-w12;
    float u10=W[o1*6], u11=W[o1*6+1], u12=W[o1*6+2];
    float t20=W[o1*6+3]-u10, t21=W[o1*6+4]-u11, t22=W[o1*6+5]-u12;
    for (int j = threadIdx.x; j < NPTS; j += 256){
        sP0[j] = w10*s0[j] + w11*s1[j] + w12*s2[j];
        sP1[j] = u10*s0[j] + u11*s1[j] + u12*s2[j];
    }
    __syncthreads();
    float ls0=0.f, lq0=0.f, ls1=0.f, lq1=0.f;
    float* M0 = g_ymax + (size_t)o0*COLS + b*NPTS;
    float* M1 = g_ymax + (size_t)o1*COLS + b*NPTS;
    for (int j = threadIdx.x; j < NPTS; j += 256){
        float q0 = v20*s0[j] + v21*s1[j] + v22*s2[j];
        float q1 = t20*s0[j] + t21*s1[j] + t22*s2[j];
        const uint4* ip = (const uint4*)(g_idx + (size_t)(b*NPTS+j)*KNB);
        uint4 v0 = ip[0], v1 = ip[1];
        float sp0=0.f, spp0=0.f, mx0=-1e30f;
        float sp1=0.f, spp1=0.f, mx1=-1e30f;
        #define GATH2(u) { \
            unsigned i0 = (u) & 0xFFFFu, i1 = (u) >> 16; \
            float p0 = sP0[i0], p1 = sP0[i1]; \
            sp0 += p0 + p1; spp0 = fmaf(p0,p0,fmaf(p1,p1,spp0)); \
            mx0 = fmaxf(mx0, fmaxf(p0, p1)); \
            float r0 = sP1[i0], r1 = sP1[i1]; \
            sp1 += r0 + r1; spp1 = fmaf(r0,r0,fmaf(r1,r1,spp1)); \
            mx1 = fmaxf(mx1, fmaxf(r0, r1)); }
        GATH2(v0.x) GATH2(v0.y) GATH2(v0.z) GATH2(v0.w)
        GATH2(v1.x) GATH2(v1.y) GATH2(v1.z) GATH2(v1.w)
        #undef GATH2
        M0[j] = mx0 + q0;
        M1[j] = mx1 + q1;
        ls0 += sp0 + 16.f*q0;  lq0 += spp0 + 2.f*q0*sp0 + 16.f*q0*q0;
        ls1 += sp1 + 16.f*q1;  lq1 += spp1 + 2.f*q1*sp1 + 16.f*q1*q1;
    }
    double d0=(double)ls0, e0=(double)lq0, d1=(double)ls1, e1=(double)lq1;
    #pragma unroll
    for (int s=16;s>0;s>>=1){
        d0 += __shfl_down_sync(0xffffffffu, d0, s);
        e0 += __shfl_down_sync(0xffffffffu, e0, s);
        d1 += __shfl_down_sync(0xffffffffu, d1, s);
        e1 += __shfl_down_sync(0xffffffffu, e1, s);
    }
    if ((threadIdx.x & 31) == 0){
        atomicAdd(&g_dsum[soff+o0], d0);
        atomicAdd(&g_dsq[soff+o0],  e0);
        atomicAdd(&g_dsum[soff+o1], d1);
        atomicAdd(&g_dsq[soff+o1],  e1);
    }
}

// gather-max for two channels, Q-factorized, stats at soff
__global__ void k_gather2(int soff) {   // grid (O/2, NB), 256 threads
    __shared__ float sP0[NPTS], sP1[NPTS];
    __shared__ double rS0[256], rQ0[256], rS1[256], rQ1[256];
    int op = blockIdx.x, b = blockIdx.y;
    int o0 = 2*op, o1 = o0 + 1;
    size_t base0 = (size_t)o0*COLS + b*NPTS;
    size_t base1 = (size_t)o1*COLS + b*NPTS;
    const float* P0 = g_P + base0;
    const float* P1 = g_P + base1;
    for (int j = threadIdx.x; j < NPTS; j += 256){ sP0[j] = P0[j]; sP1[j] = P1[j]; }
    __syncthreads();
    float ls0 = 0.f, lq0 = 0.f, ls1 = 0.f, lq1 = 0.f;
    const float* Q0 = g_Q + base0;
    const float* Q1 = g_Q + base1;
    float* M0 = g_ymax + base0;
    float* M1 = g_ymax + base1;
    for (int j = threadIdx.x; j < NPTS; j += 256) {
        float q0 = Q0[j], q1 = Q1[j];
        const uint4* ip = (const uint4*)(g_idx + (size_t)(b*NPTS+j)*KNB);
        uint4 v0 = ip[0], v1 = ip[1];
        float sp0=0.f, spp0=0.f, mx0=-1e30f;
        float sp1=0.f, spp1=0.f, mx1=-1e30f;
        #define GATH2(u) { \
            unsigned i0 = (u) & 0xFFFFu, i1 = (u) >> 16; \
            float p0 = sP0[i0], p1 = sP0[i1]; \
            sp0 += p0 + p1; spp0 = fmaf(p0,p0,fmaf(p1,p1,spp0)); \
            mx0 = fmaxf(mx0, fmaxf(p0, p1)); \
            float r0 = sP1[i0], r1 = sP1[i1]; \
            sp1 += r0 + r1; spp1 = fmaf(r0,r0,fmaf(r1,r1,spp1)); \
            mx1 = fmaxf(mx1, fmaxf(r0, r1)); }
        GATH2(v0.x) GATH2(v0.y) GATH2(v0.z) GATH2(v0.w)
        GATH2(v1.x) GATH2(v1.y) GATH2(v1.z) GATH2(v1.w)
        #undef GATH2
        M0[j] = mx0 + q0;
        M1[j] = mx1 + q1;
        ls0 += sp0 + 16.f*q0;  lq0 += spp0 + 2.f*q0*sp0 + 16.f*q0*q0;
        ls1 += sp1 + 16.f*q1;  lq1 += spp1 + 2.f*q1*sp1 + 16.f*q1*q1;
    }
    rS0[threadIdx.x] = (double)ls0; rQ0[threadIdx.x] = (double)lq0;
    rS1[threadIdx.x] = (double)ls1; rQ1[threadIdx.x] = (double)lq1;
    __syncthreads();
    for (int s=128; s>0; s>>=1){
        if (threadIdx.x < s){
            rS0[threadIdx.x]+=rS0[threadIdx.x+s]; rQ0[threadIdx.x]+=rQ0[threadIdx.x+s];
            rS1[threadIdx.x]+=rS1[threadIdx.x+s]; rQ1[threadIdx.x]+=rQ1[threadIdx.x+s];
        }
        __syncthreads();
    }
    if (threadIdx.x==0){
        atomicAdd(&g_dsum[soff+o0], rS0[0]);
        atomicAdd(&g_dsq[soff+o0],  rQ0[0]);
        atomicAdd(&g_dsum[soff+o1], rS1[0]);
        atomicAdd(&g_dsq[soff+o1],  rQ1[0]);
    }
}

// BN (finalize inline) + lrelu + bf16-pair emit
__global__ void k_bn_act(int srcsel, int dstsel, int dstp, int soff, double inv){
    __shared__ float sm0, sr0, sm1, sr1;
    int t = blockIdx.x*blockDim.x + threadIdx.x;
    int op = t >> 13, col = t & 8191;
    int o0 = 2*op, o1 = 2*op+1;
    if (threadIdx.x == 0){
        double m0 = g_dsum[soff+o0]*inv;
        double v0 = g_dsq[soff+o0]*inv - m0*m0;
        sm0 = (float)m0; sr0 = (float)(1.0/sqrt(v0 + 1e-5));
        double m1 = g_dsum[soff+o1]*inv;
        double v1 = g_dsq[soff+o1]*inv - m1*m1;
        sm1 = (float)m1; sr1 = (float)(1.0/sqrt(v1 + 1e-5));
    }
    __syncthreads();
    const float* in = srcsel ? g_ypre : g_ymax;
    float v0 = (in[(size_t)o0*COLS+col] - sm0) * sr0;
    v0 = (v0 > 0.f) ? v0 : 0.2f*v0;
    float v1 = (in[(size_t)o1*COLS+col] - sm1) * sr1;
    v1 = (v1 > 0.f) ? v1 : 0.2f*v1;
    unsigned h, l;
    split2(v0, v1, h, l);
    if (dstsel){
        g_HPH[(size_t)op*COLS+col] = h;
        g_HPL[(size_t)op*COLS+col] = l;
    } else {
        g_XPH[(size_t)(dstp+op)*COLS+col] = h;
        g_XPL[(size_t)(dstp+op)*COLS+col] = l;
    }
}

// global pooling from bf16 pairs, two channels per block
__global__ void k_pool(){   // grid (512, NB)
    __shared__ float sMx0[256], sSm0[256], sMx1[256], sSm1[256];
    int op = blockIdx.x, b = blockIdx.y;
    const unsigned* ph = g_HPH + (size_t)op*COLS + b*NPTS;
    const unsigned* pl = g_HPL + (size_t)op*COLS + b*NPTS;
    float mx0 = -1e30f, sm0 = 0.f, mx1 = -1e30f, sm1 = 0.f;
    for (int n = threadIdx.x; n < NPTS; n += 256){
        unsigned h = ph[n], l = pl[n];
        float v0 = __uint_as_float(h << 16) + __uint_as_float(l << 16);
        float v1 = __uint_as_float(h & 0xFFFF0000u) + __uint_as_float(l & 0xFFFF0000u);
        mx0 = fmaxf(mx0, v0); sm0 += v0;
        mx1 = fmaxf(mx1, v1); sm1 += v1;
    }
    sMx0[threadIdx.x]=mx0; sSm0[threadIdx.x]=sm0;
    sMx1[threadIdx.x]=mx1; sSm1[threadIdx.x]=sm1;
    __syncthreads();
    for (int s=128;s>0;s>>=1){
        if (threadIdx.x<s){
            sMx0[threadIdx.x]=fmaxf(sMx0[threadIdx.x],sMx0[threadIdx.x+s]); sSm0[threadIdx.x]+=sSm0[threadIdx.x+s];
            sMx1[threadIdx.x]=fmaxf(sMx1[threadIdx.x],sMx1[threadIdx.x+s]); sSm1[threadIdx.x]+=sSm1[threadIdx.x+s];
        }
        __syncthreads();
    }
    if (threadIdx.x==0){
        int o0 = 2*op, o1 = 2*op+1;
        g_g[b*2048 + o0] = sMx0[0];
        g_g[b*2048 + 1024 + o0] = sSm0[0]/2048.f;
        g_g[b*2048 + o1] = sMx1[0];
        g_g[b*2048 + 1024 + o1] = sSm1[0]/2048.f;
    }
}

// generic FC
__global__ void k_fc(const float* __restrict__ W, const float* __restrict__ bias,
                     int insel, int outsel, int F, int C, int mode){
    extern __shared__ float sIn[];
    const float* in = buf_ptr(insel);
    float* out = buf_ptr(outsel);
    for (int i = threadIdx.x; i < 4*C; i += blockDim.x) sIn[i] = in[i];
    __syncthreads();
    int warp = threadIdx.x >> 5, lane = threadIdx.x & 31;
    int warps = blockDim.x >> 5;
    int f = blockIdx.x*warps + warp;
    if (f >= F) return;
    float a0=0.f,a1=0.f,a2=0.f,a3=0.f;
    const float4* Wr = (const float4*)(W + (size_t)f*C);
    int C4 = C >> 2;
    for (int c4 = lane; c4 < C4; c4 += 32) {
        float4 w = Wr[c4];
        int c = c4 << 2;
        a0 += w.x*sIn[c]       + w.y*sIn[c+1]       + w.z*sIn[c+2]       + w.w*sIn[c+3];
        a1 += w.x*sIn[C+c]     + w.y*sIn[C+c+1]     + w.z*sIn[C+c+2]     + w.w*sIn[C+c+3];
        a2 += w.x*sIn[2*C+c]   + w.y*sIn[2*C+c+1]   + w.z*sIn[2*C+c+2]   + w.w*sIn[2*C+c+3];
        a3 += w.x*sIn[3*C+c]   + w.y*sIn[3*C+c+1]   + w.z*sIn[3*C+c+2]   + w.w*sIn[3*C+c+3];
    }
    #pragma unroll
    for (int s=16;s>0;s>>=1){
        a0 += __shfl_down_sync(0xffffffffu, a0, s);
        a1 += __shfl_down_sync(0xffffffffu, a1, s);
        a2 += __shfl_down_sync(0xffffffffu, a2, s);
        a3 += __shfl_down_sync(0xffffffffu, a3, s);
    }
    if (lane == 0){
        if (mode == 2){
            float m = 0.25f*(a0+a1+a2+a3);
            float d0=a0-m, d1=a1-m, d2=a2-m, d3=a3-m;
            float var = 0.25f*(d0*d0+d1*d1+d2*d2+d3*d3);
            float rs = rsqrtf(var + 1e-5f);
            float v;
            v=d0*rs; out[0*F+f] = (v>0.f)?v:0.2f*v;
            v=d1*rs; out[1*F+f] = (v>0.f)?v:0.2f*v;
            v=d2*rs; out[2*F+f] = (v>0.f)?v:0.2f*v;
            v=d3*rs; out[3*F+f] = (v>0.f)?v:0.2f*v;
        } else {
            float bb = bias ? bias[f] : 0.f;
            a0+=bb; a1+=bb; a2+=bb; a3+=bb;
            if (mode == 1){ a0=fmaxf(a0,0.f); a1=fmaxf(a1,0.f); a2=fmaxf(a2,0.f); a3=fmaxf(a3,0.f); }
            out[0*F+f]=a0; out[1*F+f]=a1; out[2*F+f]=a2; out[3*F+f]=a3;
        }
    }
}

__global__ void k_pc2xyz(const float* __restrict__ w, const float* __restrict__ bias){
    __shared__ float sw[192];
    int b = blockIdx.x, n = threadIdx.x;
    for (int i = threadIdx.x; i < 192; i += 128) sw[i] = w[i];
    __syncthreads();
    float a0 = bias[0], a1 = bias[1], a2 = bias[2];
    for (int c=0;c<64;c++){
        float f = g_pc2f[b*8192 + c*128 + n];
        a0 += sw[c]*f; a1 += sw[64+c]*f; a2 += sw[128+c]*f;
    }
    g_pc2xyz[b*384 + 0*128 + n] = a0;
    g_pc2xyz[b*384 + 1*128 + n] = a1;
    g_pc2xyz[b*384 + 2*128 + n] = a2;
}

__global__ void k_pc3tmp(const float* __restrict__ w1, const float* __restrict__ b1){
    int b = blockIdx.x, o = blockIdx.y, n = threadIdx.x;
    float acc = b1[o];
    const float* w = w1 + o*128;
    const float* f = g_pc3f + b*65536 + n;
    for (int c=0;c<128;c++) acc += w[c]*f[c*512];
    g_pc3tmp[(b*64+o)*512+n] = fmaxf(acc, 0.f);
}

__global__ void k_pc3xyz(const float* __restrict__ w2, const float* __restrict__ b2){
    __shared__ float sw[192];
    int b = blockIdx.x, n = threadIdx.x;
    for (int i = threadIdx.x; i < 192; i += 512) sw[i] = w2[i];
    __syncthreads();
    float a0 = b2[0], a1 = b2[1], a2 = b2[2];
    for (int o=0;o<64;o++){
        float t = g_pc3tmp[(b*64+o)*512+n];
        a0 += sw[o]*t; a1 += sw[64+o]*t; a2 += sw[128+o]*t;
    }
    g_pc3xyz[b*1536 + 0*512 + n] = a0;
    g_pc3xyz[b*1536 + 1*512 + n] = a1;
    g_pc3xyz[b*1536 + 2*512 + n] = a2;
}

__global__ void k_expand1(float* __restrict__ out){
    __shared__ float px[64], py[64], pz[64], pxx[64];
    int b = blockIdx.x, i = threadIdx.x;
    float vx = g_pc1[b*192 + 0*64 + i];
    float vy = g_pc1[b*192 + 1*64 + i];
    float vz = g_pc1[b*192 + 2*64 + i];
    px[i]=vx; py[i]=vy; pz[i]=vz; pxx[i]=vx*vx+vy*vy+vz*vz;
    __syncthreads();
    float cx=px[i], cy=py[i], cz=pz[i], cxx=pxx[i];
    float best=-1e30f; int bj=0;
    for (int j=0;j<64;j++){
        float pd = 2.f*(cx*px[j]+cy*py[j]+cz*pz[j]) - cxx - pxx[j];
        if (pd > best){ best=pd; bj=j; }
    }
    out[(b*64+i)*3+0]=cx; out[(b*64+i)*3+1]=cy; out[(b*64+i)*3+2]=cz;
    float* mid = out + 768;
    const float* p2 = g_pc2xyz + b*384;
    int n0 = 2*i, n1 = 2*i+1;
    float nx=px[bj], ny=py[bj], nz=pz[bj];
    mid[(b*128+n0)*3+0] = (2.f*cx - nx) + p2[0*128+n0];
    mid[(b*128+n0)*3+1] = (2.f*cy - ny) + p2[1*128+n0];
    mid[(b*128+n0)*3+2] = (2.f*cz - nz) + p2[2*128+n0];
    mid[(b*128+n1)*3+0] = cx + p2[0*128+n1];
    mid[(b*128+n1)*3+1] = cy + p2[1*128+n1];
    mid[(b*128+n1)*3+2] = cz + p2[2*128+n1];
}

__global__ void k_expand2(float* __restrict__ out){
    __shared__ float px[128], py[128], pz[128], pxx[128];
    int b = blockIdx.x, i = threadIdx.x;
    float vx = g_pc2xyz[b*384 + 0*128 + i];
    float vy = g_pc2xyz[b*384 + 1*128 + i];
    float vz = g_pc2xyz[b*384 + 2*128 + i];
    px[i]=vx; py[i]=vy; pz[i]=vz; pxx[i]=vx*vx+vy*vy+vz*vz;
    __syncthreads();
    float cx=px[i], cy=py[i], cz=pz[i], cxx=pxx[i];
    float pd0=-1e30f,pd1=-1e30f,pd2=-1e30f; int j0=0,j1=0,j2=0;
    for (int j=0;j<128;j++){
        float pd = 2.f*(cx*px[j]+cy*py[j]+cz*pz[j]) - cxx - pxx[j];
        if (pd > pd2){
            if (pd > pd1){
                pd2=pd1; j2=j1;
                if (pd > pd0){ pd1=pd0; j1=j0; pd0=pd; j0=j; }
                else { pd1=pd; j1=j; }
            } else { pd2=pd; j2=j; }
        }
    }
    float* hi = out + 2304;
    const float* p3 = g_pc3xyz + b*1536;
    int jn[3] = {j0, j1, j2};
    #pragma unroll
    for (int m=0;m<3;m++){
        int n = 4*i+m, j = jn[m];
        hi[(b*512+n)*3+0] = (2.f*cx - px[j]) + p3[0*512+n];
        hi[(b*512+n)*3+1] = (2.f*cy - py[j]) + p3[1*512+n];
        hi[(b*512+n)*3+2] = (2.f*cz - pz[j]) + p3[2*512+n];
    }
    int n = 4*i+3;
    hi[(b*512+n)*3+0] = cx + p3[0*512+n];
    hi[(b*512+n)*3+1] = cy + p3[1*512+n];
    hi[(b*512+n)*3+2] = cz + p3[2*512+n];
}

// ---------------- host ----------------

static const double INV_EDGE = 1.0/131072.0;
static const double INV_PW   = 1.0/8192.0;

#define WO2 512
#define WO3 2560
#define WO4 10752
#define SO21 0
#define SO31 8192
#define SO5  40960
// dsum slices: conv1:0 conv2:64 conv2_1:128 conv3:256 conv3_1:384 conv4:640 conv5:1152

extern "C" void kernel_launch(void* const* d_in, const int* in_sizes, int n_in,
                              void* d_out, int out_size) {
    const float* x         = (const float*)d_in[0];
    const float* conv1_w   = (const float*)d_in[1];
    const float* conv2_w   = (const float*)d_in[2];
    const float* conv2_1_w = (const float*)d_in[3];
    const float* conv3_w   = (const float*)d_in[4];
    const float* conv3_1_w = (const float*)d_in[5];
    const float* conv4_w   = (const float*)d_in[6];
    const float* conv5_w   = (const float*)d_in[7];
    const float* linear1_w = (const float*)d_in[8];
    const float* fc1_w = (const float*)d_in[9];   const float* fc1_b = (const float*)d_in[10];
    const float* fc2_w = (const float*)d_in[11];  const float* fc2_b = (const float*)d_in[12];
    const float* fc3_w = (const float*)d_in[13];  const float* fc3_b = (const float*)d_in[14];
    const float* fc1_1_w = (const float*)d_in[15]; const float* fc1_1_b = (const float*)d_in[16];
    const float* fc2_1_w = (const float*)d_in[17]; const float* fc2_1_b = (const float*)d_in[18];
    const float* fc3_1_w = (const float*)d_in[19]; const float* fc3_1_b = (const float*)d_in[20];
    const float* gc11_w = (const float*)d_in[21];  const float* gc11_b = (const float*)d_in[22];
    const float* gc12_w = (const float*)d_in[23];  const float* gc12_b = (const float*)d_in[24];
    const float* gc21_w = (const float*)d_in[25];  const float* gc21_b = (const float*)d_in[26];
    float* out = (float*)d_out;

    // 0. one zero + one wsplit
    k_zero<<<16, 256>>>(4096);
    k_wsplit_all<<<(509952+255)/256, 256>>>(conv2_w, conv3_w, conv4_w,
                                            conv2_1_w, conv3_1_w, conv5_w);

    // 1. fused transpose+pairs, then KNN
    k_xt<<<(8*COLS)/256, 256>>>(x);
    k_knn<<<dim3(NB, 16), 128>>>();

    // 2. conv1 (fused fp32 gemm+gather): C=3 -> O=64 -> X pairs [0,32)
    k_gather1<<<dim3(32, NB), 256>>>(conv1_w, 0);
    k_bn_act<<<(32*COLS)/256, 256>>>(0, 0, 0, 0, INV_EDGE);

    // 3. conv2 (edge): C=64 -> O=64 -> X pairs [32,64)
    k_gemm_dual<<<dim3(COLS/128, 1), 256>>>(1, WO2, 64, 32);
    k_gather2<<<dim3(32, NB), 256>>>(64);
    k_bn_act<<<(32*COLS)/256, 256>>>(0, 0, 32, 64, INV_EDGE);

    // 4. conv2_1: K=128 -> O=128 -> H pairs
    k_gemm_stats<<<dim3(COLS/128, 2), 256>>>(1, SO21, 128, 64, 128);
    k_bn_act<<<(64*COLS)/256, 256>>>(1, 1, 0, 128, INV_PW);

    // 5. conv3 (edge): C=128 (h) -> O=128 -> X pairs [64,128)
    k_gemm_dual<<<dim3(COLS/128, 2), 256>>>(2, WO3, 128, 64);
    k_gather2<<<dim3(64, NB), 256>>>(256);
    k_bn_act<<<(64*COLS)/256, 256>>>(0, 0, 64, 256, INV_EDGE);

    // 6. conv3_1: K=256 -> O=256 -> H pairs
    k_gemm_stats<<<dim3(COLS/128, 4), 256>>>(1, SO31, 256, 128, 384);
    k_bn_act<<<(128*COLS)/256, 256>>>(1, 1, 0, 384, INV_PW);

    // 7. conv4 (edge): C=256 (h) -> O=512 -> X pairs [128,384)
    k_gemm_dual<<<dim3(COLS/128, 8), 256>>>(2, WO4, 256, 128);
    k_gather2<<<dim3(256, NB), 256>>>(640);
    k_bn_act<<<(256*COLS)/256, 256>>>(0, 0, 128, 640, INV_EDGE);

    // 8. conv5: K=768 -> O=1024 -> H pairs
    k_gemm_stats<<<dim3(COLS/128, 16), 256>>>(1, SO5, 768, 384, 1152);
    k_bn_act<<<(512*COLS)/256, 256>>>(1, 1, 0, 1152, INV_PW);

    // 9. global pooling from pairs
    k_pool<<<dim3(512, NB), 256>>>();

    // 10-12. fc chain + heads
    k_fc<<<2048/8, 256, 4*2048*4>>>(linear1_w, nullptr, 0, 1, 2048, 2048, 2);
    k_fc<<<1024/8, 256, 4*2048*4>>>(fc1_w, fc1_b, 1, 2, 1024, 2048, 1);
    k_fc<<<512/8, 256, 4*1024*4>>>(fc2_w, fc2_b, 2, 3, 512, 1024, 1);
    k_fc<<<256/8, 256, 4*512*4>>>(fc3_w, fc3_b, 3, 4, 256, 512, 1);
    k_fc<<<192/8, 256, 4*256*4>>>(fc3_1_w, fc3_1_b, 4, 5, 192, 256, 0);
    k_fc<<<8192/32, 1024, 4*512*4>>>(fc2_1_w, fc2_1_b, 3, 6, 8192, 512, 1);
    k_fc<<<65536/32, 1024, 4*1024*4>>>(fc1_1_w, fc1_1_b, 2, 7, 65536, 1024, 1);

    // 13. small convs
    k_pc2xyz<<<NB, 128>>>(gc21_w, gc21_b);
    k_pc3tmp<<<dim3(NB, 64), 512>>>(gc11_w, gc11_b);
    k_pc3xyz<<<NB, 512>>>(gc12_w, gc12_b);

    // 14. mirror expansions + final outputs
    k_expand1<<<NB, 64>>>(out);
    k_expand2<<<NB, 128>>>(out);
}

// round 14
// speedup vs baseline: 1.1593x; 1.1593x over previous
#include <cuda_runtime.h>
#include <cuda_bf16.h>
#include <math.h>

#define COLS 8192   // B*N
#define NPTS 2048
#define NB 4
#define KNB 16

// ---------------- static device scratch ----------------
__device__ float g_xt[3*COLS];
__device__ unsigned short g_idx[COLS*KNB];
__device__ float g_P[512*COLS];
__device__ float g_Q[512*COLS];
__device__ float g_ymax[512*COLS];
__device__ float g_ypre[1024*COLS];
__device__ float g_mean[1024];
__device__ float g_rstd[1024];
__device__ double g_dsum[1024];
__device__ double g_dsq[1024];
// pair-packed bf16 activations (u32 = bf16(k_even) | bf16(k_odd)<<16)
__device__ unsigned g_TPH[8*COLS],   g_TPL[8*COLS];
__device__ unsigned g_XPH[384*COLS], g_XPL[384*COLS];
__device__ unsigned g_HPH[512*COLS], g_HPL[512*COLS];
// pair-packed bf16 weights
__device__ unsigned g_W1H[76288], g_W1L[76288], g_W2H[76288], g_W2L[76288];
__device__ unsigned g_WSH[434176], g_WSL[434176];
// tail buffers
__device__ float g_g[NB*2048];
__device__ float g_lat[NB*2048];
__device__ float g_x1v[NB*1024];
__device__ float g_x2v[NB*512];
__device__ float g_x3v[NB*256];
__device__ float g_pc1[NB*192];
__device__ float g_pc2f[NB*8192];
__device__ float g_pc2xyz[NB*384];
__device__ float g_pc3f[NB*65536];
__device__ float g_pc3tmp[NB*64*512];
__device__ float g_pc3xyz[NB*1536];

__device__ __forceinline__ const unsigned* xpH(int s){ return s==0? g_TPH : (s==1? g_XPH : g_HPH); }
__device__ __forceinline__ const unsigned* xpL(int s){ return s==0? g_TPL : (s==1? g_XPL : g_HPL); }
__device__ __forceinline__ float* buf_ptr(int s) {
    switch (s) {
        case 0: return g_g;    case 1: return g_lat;
        case 2: return g_x1v;  case 3: return g_x2v;
        case 4: return g_x3v;  case 5: return g_pc1;
        case 6: return g_pc2f; case 7: return g_pc3f;
    }
    return g_g;
}

// ---- helpers ----
__device__ __forceinline__ void split_bf16(float v, unsigned short &h, unsigned short &l){
    __nv_bfloat16 bh = __float2bfloat16_rn(v);
    float r = v - __bfloat162float(bh);
    __nv_bfloat16 bl = __float2bfloat16_rn(r);
    h = *(unsigned short*)&bh;
    l = *(unsigned short*)&bl;
}
__device__ __forceinline__ void split2(float a, float b, unsigned &h, unsigned &l){
    unsigned short ah,al,bh,bl;
    split_bf16(a, ah, al);
    split_bf16(b, bh, bl);
    h = (unsigned)ah | ((unsigned)bh << 16);
    l = (unsigned)al | ((unsigned)bl << 16);
}
__device__ __forceinline__ void mma16816(float* c, unsigned a0, unsigned a1, unsigned a2, unsigned a3,
                                         unsigned b0, unsigned b1){
    asm volatile(
        "mma.sync.aligned.m16n8k16.row.col.f32.bf16.bf16.f32 "
        "{%0,%1,%2,%3}, {%4,%5,%6,%7}, {%8,%9}, {%0,%1,%2,%3};"
        : "+f"(c[0]), "+f"(c[1]), "+f"(c[2]), "+f"(c[3])
        : "r"(a0), "r"(a1), "r"(a2), "r"(a3), "r"(b0), "r"(b1));
}
__device__ __forceinline__ unsigned smaddr(const void* p){
    return (unsigned)__cvta_generic_to_shared(p);
}
__device__ __forceinline__ void cp16(unsigned dst, const void* src){
    asm volatile("cp.async.ca.shared.global [%0], [%1], 16;" :: "r"(dst), "l"(src));
}

// ---------------- kernels ----------------

// fused transpose + xt bf16 pairs
__global__ void k_xt(const float* __restrict__ x) {
    int t = blockIdx.x*blockDim.x + threadIdx.x;
    if (t >= 8*COLS) return;
    int pr = t >> 13, col = t & 8191;
    int b = col >> 11, n = col & 2047;
    int c0 = 2*pr, c1 = 2*pr+1;
    float v0 = (c0 < 3) ? x[(b*NPTS+n)*3 + c0] : 0.f;
    float v1 = (c1 < 3) ? x[(b*NPTS+n)*3 + c1] : 0.f;
    if (c0 < 3) g_xt[c0*COLS + col] = v0;
    if (c1 < 3) g_xt[c1*COLS + col] = v1;
    unsigned h, l;
    split2(v0, v1, h, l);
    g_TPH[t] = h; g_TPL[t] = l;
}

__global__ void k_wsplit_dual(const float* __restrict__ W, int woff, int O, int K, int ldp){
    int t = blockIdx.x*blockDim.x + threadIdx.x;
    if (t >= O*ldp) return;
    int o = t / ldp, kp = t - o*ldp;
    int kk = 2*kp;
    float w1a = 0.f, w1b = 0.f, w2a = 0.f, w2b = 0.f;
    if (kk < K){
        w1a = W[(size_t)o*2*K + kk];
        w2a = W[(size_t)o*2*K + K + kk] - w1a;
    }
    if (kk+1 < K){
        w1b = W[(size_t)o*2*K + kk+1];
        w2b = W[(size_t)o*2*K + K + kk+1] - w1b;
    }
    unsigned h, l;
    split2(w1a, w1b, h, l); g_W1H[woff+t] = h; g_W1L[woff+t] = l;
    split2(w2a, w2b, h, l); g_W2H[woff+t] = h; g_W2L[woff+t] = l;
}

__global__ void k_wsplit_stats(const float* __restrict__ W, int woff, int O, int K, int ldp){
    int t = blockIdx.x*blockDim.x + threadIdx.x;
    if (t >= O*ldp) return;
    int o = t / ldp, kp = t - o*ldp;
    int kk = 2*kp;
    float wa = (kk   < K) ? W[(size_t)o*K + kk]   : 0.f;
    float wb = (kk+1 < K) ? W[(size_t)o*K + kk+1] : 0.f;
    unsigned h, l;
    split2(wa, wb, h, l); g_WSH[woff+t] = h; g_WSL[woff+t] = l;
}

// KNN k=16: 2 threads per point (lane pairs), each scans half the candidates,
// bitonic-selection merge via shuffles. Output set order-free (downstream is
// max/sum over k). Tie rule: lower index wins (chunk0 preferred).
__global__ void k_knn() {   // grid (NB, 32), 128 threads
    __shared__ float sx[NPTS], sy[NPTS], sz[NPTS], sxx[NPTS];
    int b = blockIdx.x;
    for (int j = threadIdx.x; j < NPTS; j += 128) {
        float vx = g_xt[0*COLS + b*NPTS + j];
        float vy = g_xt[1*COLS + b*NPTS + j];
        float vz = g_xt[2*COLS + b*NPTS + j];
        sx[j]=vx; sy[j]=vy; sz[j]=vz; sxx[j]=vx*vx+vy*vy+vz*vz;
    }
    __syncthreads();
    int pi = blockIdx.y*64 + (threadIdx.x >> 1);
    int half = threadIdx.x & 1;
    float cx=sx[pi], cy=sy[pi], cz=sz[pi], cxx=sxx[pi];
    float pdk[KNB]; int idk[KNB];
    #pragma unroll
    for (int m=0;m<KNB;m++){ pdk[m]=-1e30f; idk[m]=0; }
    int j0 = half << 10;
    for (int jj=0; jj<1024; jj++){
        int j = j0 + jj;
        float pd = 2.f*(cx*sx[j]+cy*sy[j]+cz*sz[j]) - cxx - sxx[j];
        if (pd > pdk[KNB-1]) {
            pdk[KNB-1]=pd; idk[KNB-1]=j;
            #pragma unroll
            for (int m=KNB-1;m>0;m--){
                bool sw = pdk[m] > pdk[m-1];
                float tp = sw ? pdk[m-1] : pdk[m];
                int   ti = sw ? idk[m-1] : idk[m];
                pdk[m-1] = sw ? pdk[m] : pdk[m-1];
                idk[m-1] = sw ? idk[m] : idk[m-1];
                pdk[m] = tp; idk[m] = ti;
            }
        }
    }
    // bitonic selection: top16(A ∪ B)[m] = max(own[m], other[15-m]); tie -> chunk0
    int res[KNB];
    #pragma unroll
    for (int m=0;m<KNB;m++){
        float opd = __shfl_xor_sync(0xffffffffu, pdk[KNB-1-m], 1);
        int   oid = __shfl_xor_sync(0xffffffffu, idk[KNB-1-m], 1);
        bool takeOwn = (half == 0) ? (pdk[m] >= opd) : (pdk[m] > opd);
        res[m] = takeOwn ? idk[m] : oid;
    }
    if (half == 0){
        #pragma unroll
        for (int m=0;m<KNB;m++)
            g_idx[(b*NPTS+pi)*KNB+m] = (unsigned short)res[m];
    }
}

// ---- tensor-core GEMMs: 64(M) x 128(N), cp.async double-buffered ----

__global__ void __launch_bounds__(256, 2)
k_gemm_dual(int xsel, int woff, int Kp, int ldp) {
    __shared__ unsigned sA1h[2][64][12], sA1l[2][64][12], sA2h[2][64][12], sA2l[2][64][12];
    __shared__ unsigned sBh[2][8][136], sBl[2][8][136];
    const unsigned* XH = xpH(xsel);
    const unsigned* XL = xpL(xsel);
    int tid = threadIdx.x;
    int warp = tid >> 5, lane = tid & 31;
    int mw = warp >> 1, nw = warp & 1;
    int gid = lane >> 2, qid = lane & 3;
    int o0 = blockIdx.y*64, n0 = blockIdx.x*128;
    int arow = (tid & 127) >> 1, ahalf = tid & 1;
    int bpr = tid >> 5, bc4 = tid & 31;
    bool hiA = (tid < 128);

    float accP[8][4], accQ[8][4];
    #pragma unroll
    for (int nt=0;nt<8;nt++)
        #pragma unroll
        for (int e=0;e<4;e++){ accP[nt][e]=0.f; accQ[nt][e]=0.f; }

    auto load_chunk = [&](int kp0, int buf){
        size_t aoff = (size_t)(woff + (o0 + arow)*ldp + kp0 + ahalf*4);
        unsigned adst = (arow*12 + ahalf*4)*4;
        if (hiA){
            cp16(smaddr(&sA1h[buf][0][0]) + adst, (const void*)(g_W1H + aoff));
            cp16(smaddr(&sA2h[buf][0][0]) + adst, (const void*)(g_W2H + aoff));
        } else {
            cp16(smaddr(&sA1l[buf][0][0]) + adst, (const void*)(g_W1L + aoff));
            cp16(smaddr(&sA2l[buf][0][0]) + adst, (const void*)(g_W2L + aoff));
        }
        size_t boff = (size_t)(kp0 + bpr)*COLS + n0 + bc4*4;
        unsigned bdst = (bpr*136 + bc4*4)*4;
        cp16(smaddr(&sBh[buf][0][0]) + bdst, (const void*)(XH + boff));
        cp16(smaddr(&sBl[buf][0][0]) + bdst, (const void*)(XL + boff));
    };

    int nch = Kp >> 4;
    load_chunk(0, 0);
    asm volatile("cp.async.commit_group;");
    for (int i = 0; i < nch; i++){
        int buf = i & 1;
        if (i + 1 < nch){
            load_chunk((i+1) << 3, (i+1) & 1);
            asm volatile("cp.async.commit_group;");
            asm volatile("cp.async.wait_group 1;");
        } else {
            asm volatile("cp.async.wait_group 0;");
        }
        __syncthreads();
        int rA = mw*16 + gid;
        unsigned a1h0=sA1h[buf][rA][qid], a1h1=sA1h[buf][rA+8][qid], a1h2=sA1h[buf][rA][qid+4], a1h3=sA1h[buf][rA+8][qid+4];
        unsigned a1l0=sA1l[buf][rA][qid], a1l1=sA1l[buf][rA+8][qid], a1l2=sA1l[buf][rA][qid+4], a1l3=sA1l[buf][rA+8][qid+4];
        unsigned a2h0=sA2h[buf][rA][qid], a2h1=sA2h[buf][rA+8][qid], a2h2=sA2h[buf][rA][qid+4], a2h3=sA2h[buf][rA+8][qid+4];
        unsigned a2l0=sA2l[buf][rA][qid], a2l1=sA2l[buf][rA+8][qid], a2l2=sA2l[buf][rA][qid+4], a2l3=sA2l[buf][rA+8][qid+4];
        #pragma unroll
        for (int nt=0;nt<8;nt++){
            int nc = nw*64 + nt*8 + gid;
            unsigned bh0 = sBh[buf][qid][nc], bh1 = sBh[buf][qid+4][nc];
            unsigned bl0 = sBl[buf][qid][nc], bl1 = sBl[buf][qid+4][nc];
            mma16816(accP[nt], a1h0,a1h1,a1h2,a1h3, bh0,bh1);
            mma16816(accP[nt], a1l0,a1l1,a1l2,a1l3, bh0,bh1);
            mma16816(accP[nt], a1h0,a1h1,a1h2,a1h3, bl0,bl1);
            mma16816(accQ[nt], a2h0,a2h1,a2h2,a2h3, bh0,bh1);
            mma16816(accQ[nt], a2l0,a2l1,a2l2,a2l3, bh0,bh1);
            mma16816(accQ[nt], a2h0,a2h1,a2h2,a2h3, bl0,bl1);
        }
        __syncthreads();
    }
    int r0 = o0 + mw*16 + gid, r1 = r0 + 8;
    #pragma unroll
    for (int nt=0;nt<8;nt++){
        int col = n0 + nw*64 + nt*8 + 2*qid;
        *(float2*)&g_P[(size_t)r0*COLS + col] = make_float2(accP[nt][0], accP[nt][1]);
        *(float2*)&g_P[(size_t)r1*COLS + col] = make_float2(accP[nt][2], accP[nt][3]);
        *(float2*)&g_Q[(size_t)r0*COLS + col] = make_float2(accQ[nt][0], accQ[nt][1]);
        *(float2*)&g_Q[(size_t)r1*COLS + col] = make_float2(accQ[nt][2], accQ[nt][3]);
    }
}

__global__ void __launch_bounds__(256, 2)
k_gemm_stats(int xsel, int woff, int Kp, int ldp) {
    __shared__ unsigned sAh[2][64][12], sAl[2][64][12];
    __shared__ unsigned sBh[2][8][136], sBl[2][8][136];
    __shared__ float sSum[64], sSq[64];
    const unsigned* XH = xpH(xsel);
    const unsigned* XL = xpL(xsel);
    int tid = threadIdx.x;
    int warp = tid >> 5, lane = tid & 31;
    int mw = warp >> 1, nw = warp & 1;
    int gid = lane >> 2, qid = lane & 3;
    int o0 = blockIdx.y*64, n0 = blockIdx.x*128;
    int arow = (tid & 127) >> 1, ahalf = tid & 1;
    int bpr = tid >> 5, bc4 = tid & 31;
    bool hiA = (tid < 128);

    float acc[8][4];
    #pragma unroll
    for (int nt=0;nt<8;nt++)
        #pragma unroll
        for (int e=0;e<4;e++) acc[nt][e]=0.f;

    auto load_chunk = [&](int kp0, int buf){
        size_t aoff = (size_t)(woff + (o0 + arow)*ldp + kp0 + ahalf*4);
        unsigned adst = (arow*12 + ahalf*4)*4;
        if (hiA) cp16(smaddr(&sAh[buf][0][0]) + adst, (const void*)(g_WSH + aoff));
        else     cp16(smaddr(&sAl[buf][0][0]) + adst, (const void*)(g_WSL + aoff));
        size_t boff = (size_t)(kp0 + bpr)*COLS + n0 + bc4*4;
        unsigned bdst = (bpr*136 + bc4*4)*4;
        cp16(smaddr(&sBh[buf][0][0]) + bdst, (const void*)(XH + boff));
        cp16(smaddr(&sBl[buf][0][0]) + bdst, (const void*)(XL + boff));
    };

    int nch = Kp >> 4;
    load_chunk(0, 0);
    asm volatile("cp.async.commit_group;");
    for (int i = 0; i < nch; i++){
        int buf = i & 1;
        if (i + 1 < nch){
            load_chunk((i+1) << 3, (i+1) & 1);
            asm volatile("cp.async.commit_group;");
            asm volatile("cp.async.wait_group 1;");
        } else {
            asm volatile("cp.async.wait_group 0;");
        }
        __syncthreads();
        int rA = mw*16 + gid;
        unsigned ah0=sAh[buf][rA][qid], ah1=sAh[buf][rA+8][qid], ah2=sAh[buf][rA][qid+4], ah3=sAh[buf][rA+8][qid+4];
        unsigned al0=sAl[buf][rA][qid], al1=sAl[buf][rA+8][qid], al2=sAl[buf][rA][qid+4], al3=sAl[buf][rA+8][qid+4];
        #pragma unroll
        for (int nt=0;nt<8;nt++){
            int nc = nw*64 + nt*8 + gid;
            unsigned bh0 = sBh[buf][qid][nc], bh1 = sBh[buf][qid+4][nc];
            unsigned bl0 = sBl[buf][qid][nc], bl1 = sBl[buf][qid+4][nc];
            mma16816(acc[nt], ah0,ah1,ah2,ah3, bh0,bh1);
            mma16816(acc[nt], al0,al1,al2,al3, bh0,bh1);
            mma16816(acc[nt], ah0,ah1,ah2,ah3, bl0,bl1);
        }
        __syncthreads();
    }
    if (tid < 64) { sSum[tid]=0.f; sSq[tid]=0.f; }
    __syncthreads();
    int lr0 = mw*16 + gid, lr1 = lr0 + 8;
    int r0 = o0 + lr0, r1 = o0 + lr1;
    float s0=0.f,q0=0.f,s1=0.f,q1=0.f;
    #pragma unroll
    for (int nt=0;nt<8;nt++){
        int col = n0 + nw*64 + nt*8 + 2*qid;
        float c0=acc[nt][0], c1=acc[nt][1], c2=acc[nt][2], c3=acc[nt][3];
        s0 += c0+c1; q0 += c0*c0+c1*c1;
        s1 += c2+c3; q1 += c2*c2+c3*c3;
        *(float2*)&g_ypre[(size_t)r0*COLS + col] = make_float2(c0, c1);
        *(float2*)&g_ypre[(size_t)r1*COLS + col] = make_float2(c2, c3);
    }
    atomicAdd(&sSum[lr0], s0); atomicAdd(&sSq[lr0], q0);
    atomicAdd(&sSum[lr1], s1); atomicAdd(&sSq[lr1], q1);
    __syncthreads();
    if (tid < 64) {
        atomicAdd(&g_dsum[o0+tid], (double)sSum[tid]);
        atomicAdd(&g_dsq[o0+tid],  (double)sSq[tid]);
    }
}

// conv1 fused gemm+gather (fp32 exact)
__global__ void __launch_bounds__(256) k_gather1(const float* __restrict__ W){  // grid (32, NB)
    __shared__ float s0[NPTS], s1[NPTS], s2[NPTS];
    __shared__ float sP0[NPTS], sP1[NPTS];
    int op = blockIdx.x, b = blockIdx.y;
    int o0 = 2*op, o1 = o0 + 1;
    for (int j = threadIdx.x; j < NPTS; j += 256){
        s0[j] = g_xt[0*COLS + b*NPTS + j];
        s1[j] = g_xt[1*COLS + b*NPTS + j];
        s2[j] = g_xt[2*COLS + b*NPTS + j];
    }
    __syncthreads();
    float w10=W[o0*6], w11=W[o0*6+1], w12=W[o0*6+2];
    float v20=W[o0*6+3]-w10, v21=W[o0*6+4]-w11, v22=W[o0*6+5]-w12;
    float u10=W[o1*6], u11=W[o1*6+1], u12=W[o1*6+2];
    float t20=W[o1*6+3]-u10, t21=W[o1*6+4]-u11, t22=W[o1*6+5]-u12;
    for (int j = threadIdx.x; j < NPTS; j += 256){
        sP0[j] = w10*s0[j] + w11*s1[j] + w12*s2[j];
        sP1[j] = u10*s0[j] + u11*s1[j] + u12*s2[j];
    }
    __syncthreads();
    float ls0=0.f, lq0=0.f, ls1=0.f, lq1=0.f;
    float* M0 = g_ymax + (size_t)o0*COLS + b*NPTS;
    float* M1 = g_ymax + (size_t)o1*COLS + b*NPTS;
    for (int j = threadIdx.x; j < NPTS; j += 256){
        float q0 = v20*s0[j] + v21*s1[j] + v22*s2[j];
        float q1 = t20*s0[j] + t21*s1[j] + t22*s2[j];
        const uint4* ip = (const uint4*)(g_idx + (size_t)(b*NPTS+j)*KNB);
        uint4 v0 = ip[0], v1 = ip[1];
        float sp0=0.f, spp0=0.f, mx0=-1e30f;
        float sp1=0.f, spp1=0.f, mx1=-1e30f;
        #define GATH2(u) { \
            unsigned i0 = (u) & 0xFFFFu, i1 = (u) >> 16; \
            float p0 = sP0[i0], p1 = sP0[i1]; \
            sp0 += p0 + p1; spp0 = fmaf(p0,p0,fmaf(p1,p1,spp0)); \
            mx0 = fmaxf(mx0, fmaxf(p0, p1)); \
            float r0 = sP1[i0], r1 = sP1[i1]; \
            sp1 += r0 + r1; spp1 = fmaf(r0,r0,fmaf(r1,r1,spp1)); \
            mx1 = fmaxf(mx1, fmaxf(r0, r1)); }
        GATH2(v0.x) GATH2(v0.y) GATH2(v0.z) GATH2(v0.w)
        GATH2(v1.x) GATH2(v1.y) GATH2(v1.z) GATH2(v1.w)
        #undef GATH2
        M0[j] = mx0 + q0;
        M1[j] = mx1 + q1;
        ls0 += sp0 + 16.f*q0;  lq0 += spp0 + 2.f*q0*sp0 + 16.f*q0*q0;
        ls1 += sp1 + 16.f*q1;  lq1 += spp1 + 2.f*q1*sp1 + 16.f*q1*q1;
    }
    double d0=(double)ls0, e0=(double)lq0, d1=(double)ls1, e1=(double)lq1;
    #pragma unroll
    for (int s=16;s>0;s>>=1){
        d0 += __shfl_down_sync(0xffffffffu, d0, s);
        e0 += __shfl_down_sync(0xffffffffu, e0, s);
        d1 += __shfl_down_sync(0xffffffffu, d1, s);
        e1 += __shfl_down_sync(0xffffffffu, e1, s);
    }
    if ((threadIdx.x & 31) == 0){
        atomicAdd(&g_dsum[o0], d0);
        atomicAdd(&g_dsq[o0],  e0);
        atomicAdd(&g_dsum[o1], d1);
        atomicAdd(&g_dsq[o1],  e1);
    }
}

// gather-max for two channels, Q-factorized
__global__ void k_gather2() {   // grid (O/2, NB), 256 threads
    __shared__ float sP0[NPTS], sP1[NPTS];
    __shared__ double rS0[256], rQ0[256], rS1[256], rQ1[256];
    int op = blockIdx.x, b = blockIdx.y;
    int o0 = 2*op, o1 = o0 + 1;
    size_t base0 = (size_t)o0*COLS + b*NPTS;
    size_t base1 = (size_t)o1*COLS + b*NPTS;
    const float* P0 = g_P + base0;
    const float* P1 = g_P + base1;
    for (int j = threadIdx.x; j < NPTS; j += 256){ sP0[j] = P0[j]; sP1[j] = P1[j]; }
    __syncthreads();
    float ls0 = 0.f, lq0 = 0.f, ls1 = 0.f, lq1 = 0.f;
    const float* Q0 = g_Q + base0;
    const float* Q1 = g_Q + base1;
    float* M0 = g_ymax + base0;
    float* M1 = g_ymax + base1;
    for (int j = threadIdx.x; j < NPTS; j += 256) {
        float q0 = Q0[j], q1 = Q1[j];
        const uint4* ip = (const uint4*)(g_idx + (size_t)(b*NPTS+j)*KNB);
        uint4 v0 = ip[0], v1 = ip[1];
        float sp0=0.f, spp0=0.f, mx0=-1e30f;
        float sp1=0.f, spp1=0.f, mx1=-1e30f;
        #define GATH2(u) { \
            unsigned i0 = (u) & 0xFFFFu, i1 = (u) >> 16; \
            float p0 = sP0[i0], p1 = sP0[i1]; \
            sp0 += p0 + p1; spp0 = fmaf(p0,p0,fmaf(p1,p1,spp0)); \
            mx0 = fmaxf(mx0, fmaxf(p0, p1)); \
            float r0 = sP1[i0], r1 = sP1[i1]; \
            sp1 += r0 + r1; spp1 = fmaf(r0,r0,fmaf(r1,r1,spp1)); \
            mx1 = fmaxf(mx1, fmaxf(r0, r1)); }
        GATH2(v0.x) GATH2(v0.y) GATH2(v0.z) GATH2(v0.w)
        GATH2(v1.x) GATH2(v1.y) GATH2(v1.z) GATH2(v1.w)
        #undef GATH2
        M0[j] = mx0 + q0;
        M1[j] = mx1 + q1;
        ls0 += sp0 + 16.f*q0;  lq0 += spp0 + 2.f*q0*sp0 + 16.f*q0*q0;
        ls1 += sp1 + 16.f*q1;  lq1 += spp1 + 2.f*q1*sp1 + 16.f*q1*q1;
    }
    rS0[threadIdx.x] = (double)ls0; rQ0[threadIdx.x] = (double)lq0;
    rS1[threadIdx.x] = (double)ls1; rQ1[threadIdx.x] = (double)lq1;
    __syncthreads();
    for (int s=128; s>0; s>>=1){
        if (threadIdx.x < s){
            rS0[threadIdx.x]+=rS0[threadIdx.x+s]; rQ0[threadIdx.x]+=rQ0[threadIdx.x+s];
            rS1[threadIdx.x]+=rS1[threadIdx.x+s]; rQ1[threadIdx.x]+=rQ1[threadIdx.x+s];
        }
        __syncthreads();
    }
    if (threadIdx.x==0){
        atomicAdd(&g_dsum[o0], rS0[0]);
        atomicAdd(&g_dsq[o0],  rQ0[0]);
        atomicAdd(&g_dsum[o1], rS1[0]);
        atomicAdd(&g_dsq[o1],  rQ1[0]);
    }
}

__global__ void k_zero(int O){
    int o = blockIdx.x*blockDim.x + threadIdx.x;
    if (o < O){ g_dsum[o]=0.0; g_dsq[o]=0.0; }
}

__global__ void k_finalize(int O, double inv){
    int o = blockIdx.x*blockDim.x + threadIdx.x;
    if (o < O){
        double mean = g_dsum[o]*inv;
        double var  = g_dsq[o]*inv - mean*mean;
        g_mean[o] = (float)mean;
        g_rstd[o] = (float)(1.0/sqrt(var + 1e-5));
    }
}

// BN + lrelu + bf16-pair emit
__global__ void k_bn_act(int srcsel, int dstsel, int dstp, int O){
    int t = blockIdx.x*blockDim.x + threadIdx.x;
    if (t >= (O>>1)*COLS) return;
    int op = t >> 13, col = t & 8191;
    const float* in = srcsel ? g_ypre : g_ymax;
    int o0 = 2*op, o1 = 2*op+1;
    float v0 = (in[(size_t)o0*COLS+col] - g_mean[o0]) * g_rstd[o0];
    v0 = (v0 > 0.f) ? v0 : 0.2f*v0;
    float v1 = (in[(size_t)o1*COLS+col] - g_mean[o1]) * g_rstd[o1];
    v1 = (v1 > 0.f) ? v1 : 0.2f*v1;
    unsigned h, l;
    split2(v0, v1, h, l);
    if (dstsel){
        g_HPH[(size_t)op*COLS+col] = h;
        g_HPL[(size_t)op*COLS+col] = l;
    } else {
        g_XPH[(size_t)(dstp+op)*COLS+col] = h;
        g_XPL[(size_t)(dstp+op)*COLS+col] = l;
    }
}

// global pooling from bf16 pairs, two channels per block
__global__ void k_pool(){   // grid (512, NB)
    __shared__ float sMx0[256], sSm0[256], sMx1[256], sSm1[256];
    int op = blockIdx.x, b = blockIdx.y;
    const unsigned* ph = g_HPH + (size_t)op*COLS + b*NPTS;
    const unsigned* pl = g_HPL + (size_t)op*COLS + b*NPTS;
    float mx0 = -1e30f, sm0 = 0.f, mx1 = -1e30f, sm1 = 0.f;
    for (int n = threadIdx.x; n < NPTS; n += 256){
        unsigned h = ph[n], l = pl[n];
        float v0 = __uint_as_float(h << 16) + __uint_as_float(l << 16);
        float v1 = __uint_as_float(h & 0xFFFF0000u) + __uint_as_float(l & 0xFFFF0000u);
        mx0 = fmaxf(mx0, v0); sm0 += v0;
        mx1 = fmaxf(mx1, v1); sm1 += v1;
    }
    sMx0[threadIdx.x]=mx0; sSm0[threadIdx.x]=sm0;
    sMx1[threadIdx.x]=mx1; sSm1[threadIdx.x]=sm1;
    __syncthreads();
    for (int s=128;s>0;s>>=1){
        if (threadIdx.x<s){
            sMx0[threadIdx.x]=fmaxf(sMx0[threadIdx.x],sMx0[threadIdx.x+s]); sSm0[threadIdx.x]+=sSm0[threadIdx.x+s];
            sMx1[threadIdx.x]=fmaxf(sMx1[threadIdx.x],sMx1[threadIdx.x+s]); sSm1[threadIdx.x]+=sSm1[threadIdx.x+s];
        }
        __syncthreads();
    }
    if (threadIdx.x==0){
        int o0 = 2*op, o1 = 2*op+1;
        g_g[b*2048 + o0] = sMx0[0];
        g_g[b*2048 + 1024 + o0] = sSm0[0]/2048.f;
        g_g[b*2048 + o1] = sMx1[0];
        g_g[b*2048 + 1024 + o1] = sSm1[0]/2048.f;
    }
}

// generic FC
__global__ void k_fc(const float* __restrict__ W, const float* __restrict__ bias,
                     int insel, int outsel, int F, int C, int mode){
    extern __shared__ float sIn[];
    const float* in = buf_ptr(insel);
    float* out = buf_ptr(outsel);
    for (int i = threadIdx.x; i < 4*C; i += blockDim.x) sIn[i] = in[i];
    __syncthreads();
    int warp = threadIdx.x >> 5, lane = threadIdx.x & 31;
    int warps = blockDim.x >> 5;
    int f = blockIdx.x*warps + warp;
    if (f >= F) return;
    float a0=0.f,a1=0.f,a2=0.f,a3=0.f;
    const float4* Wr = (const float4*)(W + (size_t)f*C);
    int C4 = C >> 2;
    for (int c4 = lane; c4 < C4; c4 += 32) {
        float4 w = Wr[c4];
        int c = c4 << 2;
        a0 += w.x*sIn[c]       + w.y*sIn[c+1]       + w.z*sIn[c+2]       + w.w*sIn[c+3];
        a1 += w.x*sIn[C+c]     + w.y*sIn[C+c+1]     + w.z*sIn[C+c+2]     + w.w*sIn[C+c+3];
        a2 += w.x*sIn[2*C+c]   + w.y*sIn[2*C+c+1]   + w.z*sIn[2*C+c+2]   + w.w*sIn[2*C+c+3];
        a3 += w.x*sIn[3*C+c]   + w.y*sIn[3*C+c+1]   + w.z*sIn[3*C+c+2]   + w.w*sIn[3*C+c+3];
    }
    #pragma unroll
    for (int s=16;s>0;s>>=1){
        a0 += __shfl_down_sync(0xffffffffu, a0, s);
        a1 += __shfl_down_sync(0xffffffffu, a1, s);
        a2 += __shfl_down_sync(0xffffffffu, a2, s);
        a3 += __shfl_down_sync(0xffffffffu, a3, s);
    }
    if (lane == 0){
        if (mode == 2){
            float m = 0.25f*(a0+a1+a2+a3);
            float d0=a0-m, d1=a1-m, d2=a2-m, d3=a3-m;
            float var = 0.25f*(d0*d0+d1*d1+d2*d2+d3*d3);
            float rs = rsqrtf(var + 1e-5f);
            float v;
            v=d0*rs; out[0*F+f] = (v>0.f)?v:0.2f*v;
            v=d1*rs; out[1*F+f] = (v>0.f)?v:0.2f*v;
            v=d2*rs; out[2*F+f] = (v>0.f)?v:0.2f*v;
            v=d3*rs; out[3*F+f] = (v>0.f)?v:0.2f*v;
        } else {
            float bb = bias ? bias[f] : 0.f;
            a0+=bb; a1+=bb; a2+=bb; a3+=bb;
            if (mode == 1){ a0=fmaxf(a0,0.f); a1=fmaxf(a1,0.f); a2=fmaxf(a2,0.f); a3=fmaxf(a3,0.f); }
            out[0*F+f]=a0; out[1*F+f]=a1; out[2*F+f]=a2; out[3*F+f]=a3;
        }
    }
}

__global__ void k_pc2xyz(const float* __restrict__ w, const float* __restrict__ bias){
    __shared__ float sw[192];
    int b = blockIdx.x, n = threadIdx.x;
    for (int i = threadIdx.x; i < 192; i += 128) sw[i] = w[i];
    __syncthreads();
    float a0 = bias[0], a1 = bias[1], a2 = bias[2];
    for (int c=0;c<64;c++){
        float f = g_pc2f[b*8192 + c*128 + n];
        a0 += sw[c]*f; a1 += sw[64+c]*f; a2 += sw[128+c]*f;
    }
    g_pc2xyz[b*384 + 0*128 + n] = a0;
    g_pc2xyz[b*384 + 1*128 + n] = a1;
    g_pc2xyz[b*384 + 2*128 + n] = a2;
}

__global__ void k_pc3tmp(const float* __restrict__ w1, const float* __restrict__ b1){
    int b = blockIdx.x, o = blockIdx.y, n = threadIdx.x;
    float acc = b1[o];
    const float* w = w1 + o*128;
    const float* f = g_pc3f + b*65536 + n;
    for (int c=0;c<128;c++) acc += w[c]*f[c*512];
    g_pc3tmp[(b*64+o)*512+n] = fmaxf(acc, 0.f);
}

__global__ void k_pc3xyz(const float* __restrict__ w2, const float* __restrict__ b2){
    __shared__ float sw[192];
    int b = blockIdx.x, n = threadIdx.x;
    for (int i = threadIdx.x; i < 192; i += 512) sw[i] = w2[i];
    __syncthreads();
    float a0 = b2[0], a1 = b2[1], a2 = b2[2];
    for (int o=0;o<64;o++){
        float t = g_pc3tmp[(b*64+o)*512+n];
        a0 += sw[o]*t; a1 += sw[64+o]*t; a2 += sw[128+o]*t;
    }
    g_pc3xyz[b*1536 + 0*512 + n] = a0;
    g_pc3xyz[b*1536 + 1*512 + n] = a1;
    g_pc3xyz[b*1536 + 2*512 + n] = a2;
}

__global__ void k_expand1(float* __restrict__ out){
    __shared__ float px[64], py[64], pz[64], pxx[64];
    int b = blockIdx.x, i = threadIdx.x;
    float vx = g_pc1[b*192 + 0*64 + i];
    float vy = g_pc1[b*192 + 1*64 + i];
    float vz = g_pc1[b*192 + 2*64 + i];
    px[i]=vx; py[i]=vy; pz[i]=vz; pxx[i]=vx*vx+vy*vy+vz*vz;
    __syncthreads();
    float cx=px[i], cy=py[i], cz=pz[i], cxx=pxx[i];
    float best=-1e30f; int bj=0;
    for (int j=0;j<64;j++){
        float pd = 2.f*(cx*px[j]+cy*py[j]+cz*pz[j]) - cxx - pxx[j];
        if (pd > best){ best=pd; bj=j; }
    }
    out[(b*64+i)*3+0]=cx; out[(b*64+i)*3+1]=cy; out[(b*64+i)*3+2]=cz;
    float* mid = out + 768;
    const float* p2 = g_pc2xyz + b*384;
    int n0 = 2*i, n1 = 2*i+1;
    float nx=px[bj], ny=py[bj], nz=pz[bj];
    mid[(b*128+n0)*3+0] = (2.f*cx - nx) + p2[0*128+n0];
    mid[(b*128+n0)*3+1] = (2.f*cy - ny) + p2[1*128+n0];
    mid[(b*128+n0)*3+2] = (2.f*cz - nz) + p2[2*128+n0];
    mid[(b*128+n1)*3+0] = cx + p2[0*128+n1];
    mid[(b*128+n1)*3+1] = cy + p2[1*128+n1];
    mid[(b*128+n1)*3+2] = cz + p2[2*128+n1];
}

__global__ void k_expand2(float* __restrict__ out){
    __shared__ float px[128], py[128], pz[128], pxx[128];
    int b = blockIdx.x, i = threadIdx.x;
    float vx = g_pc2xyz[b*384 + 0*128 + i];
    float vy = g_pc2xyz[b*384 + 1*128 + i];
    float vz = g_pc2xyz[b*384 + 2*128 + i];
    px[i]=vx; py[i]=vy; pz[i]=vz; pxx[i]=vx*vx+vy*vy+vz*vz;
    __syncthreads();
    float cx=px[i], cy=py[i], cz=pz[i], cxx=pxx[i];
    float pd0=-1e30f,pd1=-1e30f,pd2=-1e30f; int j0=0,j1=0,j2=0;
    for (int j=0;j<128;j++){
        float pd = 2.f*(cx*px[j]+cy*py[j]+cz*pz[j]) - cxx - pxx[j];
        if (pd > pd2){
            if (pd > pd1){
                pd2=pd1; j2=j1;
                if (pd > pd0){ pd1=pd0; j1=j0; pd0=pd; j0=j; }
                else { pd1=pd; j1=j; }
            } else { pd2=pd; j2=j; }
        }
    }
    float* hi = out + 2304;
    const float* p3 = g_pc3xyz + b*1536;
    int jn[3] = {j0, j1, j2};
    #pragma unroll
    for (int m=0;m<3;m++){
        int n = 4*i+m, j = jn[m];
        hi[(b*512+n)*3+0] = (2.f*cx - px[j]) + p3[0*512+n];
        hi[(b*512+n)*3+1] = (2.f*cy - py[j]) + p3[1*512+n];
        hi[(b*512+n)*3+2] = (2.f*cz - pz[j]) + p3[2*512+n];
    }
    int n = 4*i+3;
    hi[(b*512+n)*3+0] = cx + p3[0*512+n];
    hi[(b*512+n)*3+1] = cy + p3[1*512+n];
    hi[(b*512+n)*3+2] = cz + p3[2*512+n];
}

// ---------------- host ----------------

static const double INV_EDGE = 1.0/131072.0;
static const double INV_PW   = 1.0/8192.0;

#define WO2 512
#define WO3 2560
#define WO4 10752
#define SO21 0
#define SO31 8192
#define SO5  40960

extern "C" void kernel_launch(void* const* d_in, const int* in_sizes, int n_in,
                              void* d_out, int out_size) {
    const float* x         = (const float*)d_in[0];
    const float* conv1_w   = (const float*)d_in[1];
    const float* conv2_w   = (const float*)d_in[2];
    const float* conv2_1_w = (const float*)d_in[3];
    const float* conv3_w   = (const float*)d_in[4];
    const float* conv3_1_w = (const float*)d_in[5];
    const float* conv4_w   = (const float*)d_in[6];
    const float* conv5_w   = (const float*)d_in[7];
    const float* linear1_w = (const float*)d_in[8];
    const float* fc1_w = (const float*)d_in[9];   const float* fc1_b = (const float*)d_in[10];
    const float* fc2_w = (const float*)d_in[11];  const float* fc2_b = (const float*)d_in[12];
    const float* fc3_w = (const float*)d_in[13];  const float* fc3_b = (const float*)d_in[14];
    const float* fc1_1_w = (const float*)d_in[15]; const float* fc1_1_b = (const float*)d_in[16];
    const float* fc2_1_w = (const float*)d_in[17]; const float* fc2_1_b = (const float*)d_in[18];
    const float* fc3_1_w = (const float*)d_in[19]; const float* fc3_1_b = (const float*)d_in[20];
    const float* gc11_w = (const float*)d_in[21];  const float* gc11_b = (const float*)d_in[22];
    const float* gc12_w = (const float*)d_in[23];  const float* gc12_b = (const float*)d_in[24];
    const float* gc21_w = (const float*)d_in[25];  const float* gc21_b = (const float*)d_in[26];
    float* out = (float*)d_out;

    // 0. weight splits
    k_wsplit_dual<<<(64*32+255)/256, 256>>>(conv2_w, WO2, 64, 64, 32);
    k_wsplit_dual<<<(128*64+255)/256, 256>>>(conv3_w, WO3, 128, 128, 64);
    k_wsplit_dual<<<(512*128+255)/256, 256>>>(conv4_w, WO4, 512, 256, 128);
    k_wsplit_stats<<<(128*64+255)/256, 256>>>(conv2_1_w, SO21, 128, 128, 64);
    k_wsplit_stats<<<(256*128+255)/256, 256>>>(conv3_1_w, SO31, 256, 256, 128);
    k_wsplit_stats<<<(1024*384+255)/256, 256>>>(conv5_w, SO5, 1024, 768, 384);

    // 1. fused transpose+pairs, then KNN (2 threads/point, bitonic-select merge)
    k_xt<<<(8*COLS)/256, 256>>>(x);
    k_knn<<<dim3(NB, 32), 128>>>();

    // 2. conv1 (fused fp32 gemm+gather): C=3 -> O=64 -> X pairs [0,32)
    k_zero<<<1, 256>>>(64);
    k_gather1<<<dim3(32, NB), 256>>>(conv1_w);
    k_finalize<<<1, 256>>>(64, INV_EDGE);
    k_bn_act<<<(32*COLS)/256, 256>>>(0, 0, 0, 64);

    // 3. conv2 (edge): C=64 -> O=64 -> X pairs [32,64)
    k_zero<<<1, 256>>>(64);
    k_gemm_dual<<<dim3(COLS/128, 1), 256>>>(1, WO2, 64, 32);
    k_gather2<<<dim3(32, NB), 256>>>();
    k_finalize<<<1, 256>>>(64, INV_EDGE);
    k_bn_act<<<(32*COLS)/256, 256>>>(0, 0, 32, 64);

    // 4. conv2_1: K=128 -> O=128 -> H pairs
    k_zero<<<1, 256>>>(128);
    k_gemm_stats<<<dim3(COLS/128, 2), 256>>>(1, SO21, 128, 64);
    k_finalize<<<1, 256>>>(128, INV_PW);
    k_bn_act<<<(64*COLS)/256, 256>>>(1, 1, 0, 128);

    // 5. conv3 (edge): C=128 (h) -> O=128 -> X pairs [64,128)
    k_zero<<<1, 256>>>(128);
    k_gemm_dual<<<dim3(COLS/128, 2), 256>>>(2, WO3, 128, 64);
    k_gather2<<<dim3(64, NB), 256>>>();
    k_finalize<<<1, 256>>>(128, INV_EDGE);
    k_bn_act<<<(64*COLS)/256, 256>>>(0, 0, 64, 128);

    // 6. conv3_1: K=256 -> O=256 -> H pairs
    k_zero<<<1, 256>>>(256);
    k_gemm_stats<<<dim3(COLS/128, 4), 256>>>(1, SO31, 256, 128);
    k_finalize<<<1, 256>>>(256, INV_PW);
    k_bn_act<<<(128*COLS)/256, 256>>>(1, 1, 0, 256);

    // 7. conv4 (edge): C=256 (h) -> O=512 -> X pairs [128,384)
    k_zero<<<2, 256>>>(512);
    k_gemm_dual<<<dim3(COLS/128, 8), 256>>>(2, WO4, 256, 128);
    k_gather2<<<dim3(256, NB), 256>>>();
    k_finalize<<<2, 256>>>(512, INV_EDGE);
    k_bn_act<<<(256*COLS)/256, 256>>>(0, 0, 128, 512);

    // 8. conv5: K=768 -> O=1024 -> H pairs
    k_zero<<<4, 256>>>(1024);
    k_gemm_stats<<<dim3(COLS/128, 16), 256>>>(1, SO5, 768, 384);
    k_finalize<<<4, 256>>>(1024, INV_PW);
    k_bn_act<<<(512*COLS)/256, 256>>>(1, 1, 0, 1024);

    // 9. global pooling from pairs
    k_pool<<<dim3(512, NB), 256>>>();

    // 10-12. fc chain + heads
    k_fc<<<2048/8, 256, 4*2048*4>>>(linear1_w, nullptr, 0, 1, 2048, 2048, 2);
    k_fc<<<1024/8, 256, 4*2048*4>>>(fc1_w, fc1_b, 1, 2, 1024, 2048, 1);
    k_fc<<<512/8, 256, 4*1024*4>>>(fc2_w, fc2_b, 2, 3, 512, 1024, 1);
    k_fc<<<256/8, 256, 4*512*4>>>(fc3_w, fc3_b, 3, 4, 256, 512, 1);
    k_fc<<<192/8, 256, 4*256*4>>>(fc3_1_w, fc3_1_b, 4, 5, 192, 256, 0);
    k_fc<<<8192/32, 1024, 4*512*4>>>(fc2_1_w, fc2_1_b, 3, 6, 8192, 512, 1);
    k_fc<<<65536/32, 1024, 4*1024*4>>>(fc1_1_w, fc1_1_b, 2, 7, 65536, 1024, 1);

    // 13. small convs
    k_pc2xyz<<<NB, 128>>>(gc21_w, gc21_b);
    k_pc3tmp<<<dim3(NB, 64), 512>>>(gc11_w, gc11_b);
    k_pc3xyz<<<NB, 512>>>(gc12_w, gc12_b);

    // 14. mirror expansions + final outputs
    k_expand1<<<NB, 64>>>(out);
    k_expand2<<<NB, 128>>>(out);
}

// round 15
// speedup vs baseline: 1.2478x; 1.0763x over previous
#include <cuda_runtime.h>
#include <cuda_bf16.h>
#include <math.h>

#define COLS 8192   // B*N
#define NPTS 2048
#define NB 4
#define KNB 16

// ---------------- static device scratch ----------------
__device__ float g_xt[3*COLS];
__device__ unsigned short g_idx[COLS*KNB];
__device__ float g_P[512*COLS];
__device__ float g_Q[512*COLS];
__device__ float g_ymax[512*COLS];
__device__ float g_ypre[1024*COLS];
__device__ float g_mean[1024];
__device__ float g_rstd[1024];
__device__ double g_dsum[1024];
__device__ double g_dsq[1024];
// pair-packed bf16 activations (u32 = bf16(k_even) | bf16(k_odd)<<16)
__device__ unsigned g_TPH[8*COLS],   g_TPL[8*COLS];
__device__ unsigned g_XPH[384*COLS], g_XPL[384*COLS];
__device__ unsigned g_HPH[512*COLS], g_HPL[512*COLS];
// pair-packed bf16 weights
__device__ unsigned g_W1H[76288], g_W1L[76288], g_W2H[76288], g_W2L[76288];
__device__ unsigned g_WSH[434176], g_WSL[434176];
// tail buffers
__device__ float g_g[NB*2048];
__device__ float g_lat[NB*2048];
__device__ float g_x1v[NB*1024];
__device__ float g_x2v[NB*512];
__device__ float g_x3v[NB*256];
__device__ float g_pc1[NB*192];
__device__ float g_pc2f[NB*8192];
__device__ float g_pc2xyz[NB*384];
__device__ float g_pc3f[NB*65536];
__device__ float g_pc3tmp[NB*64*512];
__device__ float g_pc3xyz[NB*1536];

__device__ __forceinline__ const unsigned* xpH(int s){ return s==0? g_TPH : (s==1? g_XPH : g_HPH); }
__device__ __forceinline__ const unsigned* xpL(int s){ return s==0? g_TPL : (s==1? g_XPL : g_HPL); }
__device__ __forceinline__ float* buf_ptr(int s) {
    switch (s) {
        case 0: return g_g;    case 1: return g_lat;
        case 2: return g_x1v;  case 3: return g_x2v;
        case 4: return g_x3v;  case 5: return g_pc1;
        case 6: return g_pc2f; case 7: return g_pc3f;
    }
    return g_g;
}

// ---- helpers ----
__device__ __forceinline__ void split_bf16(float v, unsigned short &h, unsigned short &l){
    __nv_bfloat16 bh = __float2bfloat16_rn(v);
    float r = v - __bfloat162float(bh);
    __nv_bfloat16 bl = __float2bfloat16_rn(r);
    h = *(unsigned short*)&bh;
    l = *(unsigned short*)&bl;
}
__device__ __forceinline__ void split2(float a, float b, unsigned &h, unsigned &l){
    unsigned short ah,al,bh,bl;
    split_bf16(a, ah, al);
    split_bf16(b, bh, bl);
    h = (unsigned)ah | ((unsigned)bh << 16);
    l = (unsigned)al | ((unsigned)bl << 16);
}
__device__ __forceinline__ void mma16816(float* c, unsigned a0, unsigned a1, unsigned a2, unsigned a3,
                                         unsigned b0, unsigned b1){
    asm volatile(
        "mma.sync.aligned.m16n8k16.row.col.f32.bf16.bf16.f32 "
        "{%0,%1,%2,%3}, {%4,%5,%6,%7}, {%8,%9}, {%0,%1,%2,%3};"
        : "+f"(c[0]), "+f"(c[1]), "+f"(c[2]), "+f"(c[3])
        : "r"(a0), "r"(a1), "r"(a2), "r"(a3), "r"(b0), "r"(b1));
}
__device__ __forceinline__ unsigned smaddr(const void* p){
    return (unsigned)__cvta_generic_to_shared(p);
}
__device__ __forceinline__ void cp16(unsigned dst, const void* src){
    asm volatile("cp.async.ca.shared.global [%0], [%1], 16;" :: "r"(dst), "l"(src));
}

// ---------------- kernels ----------------

// fused transpose + xt bf16 pairs
__global__ void k_xt(const float* __restrict__ x) {
    int t = blockIdx.x*blockDim.x + threadIdx.x;
    if (t >= 8*COLS) return;
    int pr = t >> 13, col = t & 8191;
    int b = col >> 11, n = col & 2047;
    int c0 = 2*pr, c1 = 2*pr+1;
    float v0 = (c0 < 3) ? x[(b*NPTS+n)*3 + c0] : 0.f;
    float v1 = (c1 < 3) ? x[(b*NPTS+n)*3 + c1] : 0.f;
    if (c0 < 3) g_xt[c0*COLS + col] = v0;
    if (c1 < 3) g_xt[c1*COLS + col] = v1;
    unsigned h, l;
    split2(v0, v1, h, l);
    g_TPH[t] = h; g_TPL[t] = l;
}

__global__ void k_wsplit_dual(const float* __restrict__ W, int woff, int O, int K, int ldp){
    int t = blockIdx.x*blockDim.x + threadIdx.x;
    if (t >= O*ldp) return;
    int o = t / ldp, kp = t - o*ldp;
    int kk = 2*kp;
    float w1a = 0.f, w1b = 0.f, w2a = 0.f, w2b = 0.f;
    if (kk < K){
        w1a = W[(size_t)o*2*K + kk];
        w2a = W[(size_t)o*2*K + K + kk] - w1a;
    }
    if (kk+1 < K){
        w1b = W[(size_t)o*2*K + kk+1];
        w2b = W[(size_t)o*2*K + K + kk+1] - w1b;
    }
    unsigned h, l;
    split2(w1a, w1b, h, l); g_W1H[woff+t] = h; g_W1L[woff+t] = l;
    split2(w2a, w2b, h, l); g_W2H[woff+t] = h; g_W2L[woff+t] = l;
}

__global__ void k_wsplit_stats(const float* __restrict__ W, int woff, int O, int K, int ldp){
    int t = blockIdx.x*blockDim.x + threadIdx.x;
    if (t >= O*ldp) return;
    int o = t / ldp, kp = t - o*ldp;
    int kk = 2*kp;
    float wa = (kk   < K) ? W[(size_t)o*K + kk]   : 0.f;
    float wb = (kk+1 < K) ? W[(size_t)o*K + kk+1] : 0.f;
    unsigned h, l;
    split2(wa, wb, h, l); g_WSH[woff+t] = h; g_WSL[woff+t] = l;
}

// KNN k=16: 4 threads per point, each scans 512 candidates; two-stage
// bitonic-selection merge via shuffles with tie-aware (stable) ordering.
// Comparator everywhere: higher pd first; equal pd -> lower index first.
__global__ void k_knn() {   // grid (NB, 32), 256 threads
    __shared__ float sx[NPTS], sy[NPTS], sz[NPTS], sxx[NPTS];
    int b = blockIdx.x;
    for (int j = threadIdx.x; j < NPTS; j += 256) {
        float vx = g_xt[0*COLS + b*NPTS + j];
        float vy = g_xt[1*COLS + b*NPTS + j];
        float vz = g_xt[2*COLS + b*NPTS + j];
        sx[j]=vx; sy[j]=vy; sz[j]=vz; sxx[j]=vx*vx+vy*vy+vz*vz;
    }
    __syncthreads();
    int pi = blockIdx.y*64 + (threadIdx.x >> 2);
    int q = threadIdx.x & 3;
    float cx=sx[pi], cy=sy[pi], cz=sz[pi], cxx=sxx[pi];
    float pdk[KNB]; int idk[KNB];
    #pragma unroll
    for (int m=0;m<KNB;m++){ pdk[m]=-1e30f; idk[m]=0x7FFFFFFF; }
    int j0 = q << 9;
    for (int jj=0; jj<512; jj++){
        int j = j0 + jj;
        float pd = 2.f*(cx*sx[j]+cy*sy[j]+cz*sz[j]) - cxx - sxx[j];
        if (pd > pdk[KNB-1]) {
            pdk[KNB-1]=pd; idk[KNB-1]=j;
            #pragma unroll
            for (int m=KNB-1;m>0;m--){
                bool sw = pdk[m] > pdk[m-1];
                float tp = sw ? pdk[m-1] : pdk[m];
                int   ti = sw ? idk[m-1] : idk[m];
                pdk[m-1] = sw ? pdk[m] : pdk[m-1];
                idk[m-1] = sw ? idk[m] : idk[m-1];
                pdk[m] = tp; idk[m] = ti;
            }
        }
    }
    // ---- stage 1 merge (xor 1): selection of pair top-16; tie -> lower chunk ----
    float pd1[KNB]; int id1[KNB];
    bool low1 = (q & 1) == 0;
    #pragma unroll
    for (int m=0;m<KNB;m++){
        float opd = __shfl_xor_sync(0xffffffffu, pdk[KNB-1-m], 1);
        int   oid = __shfl_xor_sync(0xffffffffu, idk[KNB-1-m], 1);
        bool takeOwn = low1 ? (pdk[m] >= opd) : (pdk[m] > opd);
        pd1[m] = takeOwn ? pdk[m] : opd;
        id1[m] = takeOwn ? idk[m] : oid;
    }
    // ---- bitonic cleanup: sort descending, stable (equal pd -> lower id first) ----
    #pragma unroll
    for (int d = 8; d > 0; d >>= 1){
        #pragma unroll
        for (int i = 0; i < KNB; i++){
            if ((i & d) == 0){
                bool sw = (pd1[i] < pd1[i+d]) || (pd1[i] == pd1[i+d] && id1[i] > id1[i+d]);
                float tp = sw ? pd1[i] : pd1[i+d];
                int   ti = sw ? id1[i] : id1[i+d];
                pd1[i]   = sw ? pd1[i+d] : pd1[i];
                id1[i]   = sw ? id1[i+d] : id1[i];
                pd1[i+d] = tp; id1[i+d] = ti;
            }
        }
    }
    // ---- stage 2 merge (xor 2): tie -> lower pair ----
    bool low2 = (q & 2) == 0;
    int res[KNB];
    #pragma unroll
    for (int m=0;m<KNB;m++){
        float opd = __shfl_xor_sync(0xffffffffu, pd1[KNB-1-m], 2);
        int   oid = __shfl_xor_sync(0xffffffffu, id1[KNB-1-m], 2);
        bool takeOwn = low2 ? (pd1[m] >= opd) : (pd1[m] > opd);
        res[m] = takeOwn ? id1[m] : oid;
    }
    if (q == 0){
        #pragma unroll
        for (int m=0;m<KNB;m++)
            g_idx[(b*NPTS+pi)*KNB+m] = (unsigned short)res[m];
    }
}

// ---- tensor-core GEMMs: 64(M) x 128(N), cp.async double-buffered ----

__global__ void __launch_bounds__(256, 2)
k_gemm_dual(int xsel, int woff, int Kp, int ldp) {
    __shared__ unsigned sA1h[2][64][12], sA1l[2][64][12], sA2h[2][64][12], sA2l[2][64][12];
    __shared__ unsigned sBh[2][8][136], sBl[2][8][136];
    const unsigned* XH = xpH(xsel);
    const unsigned* XL = xpL(xsel);
    int tid = threadIdx.x;
    int warp = tid >> 5, lane = tid & 31;
    int mw = warp >> 1, nw = warp & 1;
    int gid = lane >> 2, qid = lane & 3;
    int o0 = blockIdx.y*64, n0 = blockIdx.x*128;
    int arow = (tid & 127) >> 1, ahalf = tid & 1;
    int bpr = tid >> 5, bc4 = tid & 31;
    bool hiA = (tid < 128);

    float accP[8][4], accQ[8][4];
    #pragma unroll
    for (int nt=0;nt<8;nt++)
        #pragma unroll
        for (int e=0;e<4;e++){ accP[nt][e]=0.f; accQ[nt][e]=0.f; }

    auto load_chunk = [&](int kp0, int buf){
        size_t aoff = (size_t)(woff + (o0 + arow)*ldp + kp0 + ahalf*4);
        unsigned adst = (arow*12 + ahalf*4)*4;
        if (hiA){
            cp16(smaddr(&sA1h[buf][0][0]) + adst, (const void*)(g_W1H + aoff));
            cp16(smaddr(&sA2h[buf][0][0]) + adst, (const void*)(g_W2H + aoff));
        } else {
            cp16(smaddr(&sA1l[buf][0][0]) + adst, (const void*)(g_W1L + aoff));
            cp16(smaddr(&sA2l[buf][0][0]) + adst, (const void*)(g_W2L + aoff));
        }
        size_t boff = (size_t)(kp0 + bpr)*COLS + n0 + bc4*4;
        unsigned bdst = (bpr*136 + bc4*4)*4;
        cp16(smaddr(&sBh[buf][0][0]) + bdst, (const void*)(XH + boff));
        cp16(smaddr(&sBl[buf][0][0]) + bdst, (const void*)(XL + boff));
    };

    int nch = Kp >> 4;
    load_chunk(0, 0);
    asm volatile("cp.async.commit_group;");
    for (int i = 0; i < nch; i++){
        int buf = i & 1;
        if (i + 1 < nch){
            load_chunk((i+1) << 3, (i+1) & 1);
            asm volatile("cp.async.commit_group;");
            asm volatile("cp.async.wait_group 1;");
        } else {
            asm volatile("cp.async.wait_group 0;");
        }
        __syncthreads();
        int rA = mw*16 + gid;
        unsigned a1h0=sA1h[buf][rA][qid], a1h1=sA1h[buf][rA+8][qid], a1h2=sA1h[buf][rA][qid+4], a1h3=sA1h[buf][rA+8][qid+4];
        unsigned a1l0=sA1l[buf][rA][qid], a1l1=sA1l[buf][rA+8][qid], a1l2=sA1l[buf][rA][qid+4], a1l3=sA1l[buf][rA+8][qid+4];
        unsigned a2h0=sA2h[buf][rA][qid], a2h1=sA2h[buf][rA+8][qid], a2h2=sA2h[buf][rA][qid+4], a2h3=sA2h[buf][rA+8][qid+4];
        unsigned a2l0=sA2l[buf][rA][qid], a2l1=sA2l[buf][rA+8][qid], a2l2=sA2l[buf][rA][qid+4], a2l3=sA2l[buf][rA+8][qid+4];
        #pragma unroll
        for (int nt=0;nt<8;nt++){
            int nc = nw*64 + nt*8 + gid;
            unsigned bh0 = sBh[buf][qid][nc], bh1 = sBh[buf][qid+4][nc];
            unsigned bl0 = sBl[buf][qid][nc], bl1 = sBl[buf][qid+4][nc];
            mma16816(accP[nt], a1h0,a1h1,a1h2,a1h3, bh0,bh1);
            mma16816(accP[nt], a1l0,a1l1,a1l2,a1l3, bh0,bh1);
            mma16816(accP[nt], a1h0,a1h1,a1h2,a1h3, bl0,bl1);
            mma16816(accQ[nt], a2h0,a2h1,a2h2,a2h3, bh0,bh1);
            mma16816(accQ[nt], a2l0,a2l1,a2l2,a2l3, bh0,bh1);
            mma16816(accQ[nt], a2h0,a2h1,a2h2,a2h3, bl0,bl1);
        }
        __syncthreads();
    }
    int r0 = o0 + mw*16 + gid, r1 = r0 + 8;
    #pragma unroll
    for (int nt=0;nt<8;nt++){
        int col = n0 + nw*64 + nt*8 + 2*qid;
        *(float2*)&g_P[(size_t)r0*COLS + col] = make_float2(accP[nt][0], accP[nt][1]);
        *(float2*)&g_P[(size_t)r1*COLS + col] = make_float2(accP[nt][2], accP[nt][3]);
        *(float2*)&g_Q[(size_t)r0*COLS + col] = make_float2(accQ[nt][0], accQ[nt][1]);
        *(float2*)&g_Q[(size_t)r1*COLS + col] = make_float2(accQ[nt][2], accQ[nt][3]);
    }
}

__global__ void __launch_bounds__(256, 2)
k_gemm_stats(int xsel, int woff, int Kp, int ldp) {
    __shared__ unsigned sAh[2][64][12], sAl[2][64][12];
    __shared__ unsigned sBh[2][8][136], sBl[2][8][136];
    __shared__ float sSum[64], sSq[64];
    const unsigned* XH = xpH(xsel);
    const unsigned* XL = xpL(xsel);
    int tid = threadIdx.x;
    int warp = tid >> 5, lane = tid & 31;
    int mw = warp >> 1, nw = warp & 1;
    int gid = lane >> 2, qid = lane & 3;
    int o0 = blockIdx.y*64, n0 = blockIdx.x*128;
    int arow = (tid & 127) >> 1, ahalf = tid & 1;
    int bpr = tid >> 5, bc4 = tid & 31;
    bool hiA = (tid < 128);

    float acc[8][4];
    #pragma unroll
    for (int nt=0;nt<8;nt++)
        #pragma unroll
        for (int e=0;e<4;e++) acc[nt][e]=0.f;

    auto load_chunk = [&](int kp0, int buf){
        size_t aoff = (size_t)(woff + (o0 + arow)*ldp + kp0 + ahalf*4);
        unsigned adst = (arow*12 + ahalf*4)*4;
        if (hiA) cp16(smaddr(&sAh[buf][0][0]) + adst, (const void*)(g_WSH + aoff));
        else     cp16(smaddr(&sAl[buf][0][0]) + adst, (const void*)(g_WSL + aoff));
        size_t boff = (size_t)(kp0 + bpr)*COLS + n0 + bc4*4;
        unsigned bdst = (bpr*136 + bc4*4)*4;
        cp16(smaddr(&sBh[buf][0][0]) + bdst, (const void*)(XH + boff));
        cp16(smaddr(&sBl[buf][0][0]) + bdst, (const void*)(XL + boff));
    };

    int nch = Kp >> 4;
    load_chunk(0, 0);
    asm volatile("cp.async.commit_group;");
    for (int i = 0; i < nch; i++){
        int buf = i & 1;
        if (i + 1 < nch){
            load_chunk((i+1) << 3, (i+1) & 1);
            asm volatile("cp.async.commit_group;");
            asm volatile("cp.async.wait_group 1;");
        } else {
            asm volatile("cp.async.wait_group 0;");
        }
        __syncthreads();
        int rA = mw*16 + gid;
        unsigned ah0=sAh[buf][rA][qid], ah1=sAh[buf][rA+8][qid], ah2=sAh[buf][rA][qid+4], ah3=sAh[buf][rA+8][qid+4];
        unsigned al0=sAl[buf][rA][qid], al1=sAl[buf][rA+8][qid], al2=sAl[buf][rA][qid+4], al3=sAl[buf][rA+8][qid+4];
        #pragma unroll
        for (int nt=0;nt<8;nt++){
            int nc = nw*64 + nt*8 + gid;
            unsigned bh0 = sBh[buf][qid][nc], bh1 = sBh[buf][qid+4][nc];
            unsigned bl0 = sBl[buf][qid][nc], bl1 = sBl[buf][qid+4][nc];
            mma16816(acc[nt], ah0,ah1,ah2,ah3, bh0,bh1);
            mma16816(acc[nt], al0,al1,al2,al3, bh0,bh1);
            mma16816(acc[nt], ah0,ah1,ah2,ah3, bl0,bl1);
        }
        __syncthreads();
    }
    if (tid < 64) { sSum[tid]=0.f; sSq[tid]=0.f; }
    __syncthreads();
    int lr0 = mw*16 + gid, lr1 = lr0 + 8;
    int r0 = o0 + lr0, r1 = o0 + lr1;
    float s0=0.f,q0=0.f,s1=0.f,q1=0.f;
    #pragma unroll
    for (int nt=0;nt<8;nt++){
        int col = n0 + nw*64 + nt*8 + 2*qid;
        float c0=acc[nt][0], c1=acc[nt][1], c2=acc[nt][2], c3=acc[nt][3];
        s0 += c0+c1; q0 += c0*c0+c1*c1;
        s1 += c2+c3; q1 += c2*c2+c3*c3;
        *(float2*)&g_ypre[(size_t)r0*COLS + col] = make_float2(c0, c1);
        *(float2*)&g_ypre[(size_t)r1*COLS + col] = make_float2(c2, c3);
    }
    atomicAdd(&sSum[lr0], s0); atomicAdd(&sSq[lr0], q0);
    atomicAdd(&sSum[lr1], s1); atomicAdd(&sSq[lr1], q1);
    __syncthreads();
    if (tid < 64) {
        atomicAdd(&g_dsum[o0+tid], (double)sSum[tid]);
        atomicAdd(&g_dsq[o0+tid],  (double)sSq[tid]);
    }
}

// conv1 fused gemm+gather (fp32 exact)
__global__ void __launch_bounds__(256) k_gather1(const float* __restrict__ W){  // grid (32, NB)
    __shared__ float s0[NPTS], s1[NPTS], s2[NPTS];
    __shared__ float sP0[NPTS], sP1[NPTS];
    int op = blockIdx.x, b = blockIdx.y;
    int o0 = 2*op, o1 = o0 + 1;
    for (int j = threadIdx.x; j < NPTS; j += 256){
        s0[j] = g_xt[0*COLS + b*NPTS + j];
        s1[j] = g_xt[1*COLS + b*NPTS + j];
        s2[j] = g_xt[2*COLS + b*NPTS + j];
    }
    __syncthreads();
    float w10=W[o0*6], w11=W[o0*6+1], w12=W[o0*6+2];
    float v20=W[o0*6+3]-w10, v21=W[o0*6+4]-w11, v22=W[o0*6+5]-w12;
    float u10=W[o1*6], u11=W[o1*6+1], u12=W[o1*6+2];
    float t20=W[o1*6+3]-u10, t21=W[o1*6+4]-u11, t22=W[o1*6+5]-u12;
    for (int j = threadIdx.x; j < NPTS; j += 256){
        sP0[j] = w10*s0[j] + w11*s1[j] + w12*s2[j];
        sP1[j] = u10*s0[j] + u11*s1[j] + u12*s2[j];
    }
    __syncthreads();
    float ls0=0.f, lq0=0.f, ls1=0.f, lq1=0.f;
    float* M0 = g_ymax + (size_t)o0*COLS + b*NPTS;
    float* M1 = g_ymax + (size_t)o1*COLS + b*NPTS;
    for (int j = threadIdx.x; j < NPTS; j += 256){
        float q0 = v20*s0[j] + v21*s1[j] + v22*s2[j];
        float q1 = t20*s0[j] + t21*s1[j] + t22*s2[j];
        const uint4* ip = (const uint4*)(g_idx + (size_t)(b*NPTS+j)*KNB);
        uint4 v0 = ip[0], v1 = ip[1];
        float sp0=0.f, spp0=0.f, mx0=-1e30f;
        float sp1=0.f, spp1=0.f, mx1=-1e30f;
        #define GATH2(u) { \
            unsigned i0 = (u) & 0xFFFFu, i1 = (u) >> 16; \
            float p0 = sP0[i0], p1 = sP0[i1]; \
            sp0 += p0 + p1; spp0 = fmaf(p0,p0,fmaf(p1,p1,spp0)); \
            mx0 = fmaxf(mx0, fmaxf(p0, p1)); \
            float r0 = sP1[i0], r1 = sP1[i1]; \
            sp1 += r0 + r1; spp1 = fmaf(r0,r0,fmaf(r1,r1,spp1)); \
            mx1 = fmaxf(mx1, fmaxf(r0, r1)); }
        GATH2(v0.x) GATH2(v0.y) GATH2(v0.z) GATH2(v0.w)
        GATH2(v1.x) GATH2(v1.y) GATH2(v1.z) GATH2(v1.w)
        #undef GATH2
        M0[j] = mx0 + q0;
        M1[j] = mx1 + q1;
        ls0 += sp0 + 16.f*q0;  lq0 += spp0 + 2.f*q0*sp0 + 16.f*q0*q0;
        ls1 += sp1 + 16.f*q1;  lq1 += spp1 + 2.f*q1*sp1 + 16.f*q1*q1;
    }
    double d0=(double)ls0, e0=(double)lq0, d1=(double)ls1, e1=(double)lq1;
    #pragma unroll
    for (int s=16;s>0;s>>=1){
        d0 += __shfl_down_sync(0xffffffffu, d0, s);
        e0 += __shfl_down_sync(0xffffffffu, e0, s);
        d1 += __shfl_down_sync(0xffffffffu, d1, s);
        e1 += __shfl_down_sync(0xffffffffu, e1, s);
    }
    if ((threadIdx.x & 31) == 0){
        atomicAdd(&g_dsum[o0], d0);
        atomicAdd(&g_dsq[o0],  e0);
        atomicAdd(&g_dsum[o1], d1);
        atomicAdd(&g_dsq[o1],  e1);
    }
}

// gather-max for two channels, Q-factorized
__global__ void k_gather2() {   // grid (O/2, NB), 256 threads
    __shared__ float sP0[NPTS], sP1[NPTS];
    __shared__ double rS0[256], rQ0[256], rS1[256], rQ1[256];
    int op = blockIdx.x, b = blockIdx.y;
    int o0 = 2*op, o1 = o0 + 1;
    size_t base0 = (size_t)o0*COLS + b*NPTS;
    size_t base1 = (size_t)o1*COLS + b*NPTS;
    const float* P0 = g_P + base0;
    const float* P1 = g_P + base1;
    for (int j = threadIdx.x; j < NPTS; j += 256){ sP0[j] = P0[j]; sP1[j] = P1[j]; }
    __syncthreads();
    float ls0 = 0.f, lq0 = 0.f, ls1 = 0.f, lq1 = 0.f;
    const float* Q0 = g_Q + base0;
    const float* Q1 = g_Q + base1;
    float* M0 = g_ymax + base0;
    float* M1 = g_ymax + base1;
    for (int j = threadIdx.x; j < NPTS; j += 256) {
        float q0 = Q0[j], q1 = Q1[j];
        const uint4* ip = (const uint4*)(g_idx + (size_t)(b*NPTS+j)*KNB);
        uint4 v0 = ip[0], v1 = ip[1];
        float sp0=0.f, spp0=0.f, mx0=-1e30f;
        float sp1=0.f, spp1=0.f, mx1=-1e30f;
        #define GATH2(u) { \
            unsigned i0 = (u) & 0xFFFFu, i1 = (u) >> 16; \
            float p0 = sP0[i0], p1 = sP0[i1]; \
            sp0 += p0 + p1; spp0 = fmaf(p0,p0,fmaf(p1,p1,spp0)); \
            mx0 = fmaxf(mx0, fmaxf(p0, p1)); \
            float r0 = sP1[i0], r1 = sP1[i1]; \
            sp1 += r0 + r1; spp1 = fmaf(r0,r0,fmaf(r1,r1,spp1)); \
            mx1 = fmaxf(mx1, fmaxf(r0, r1)); }
        GATH2(v0.x) GATH2(v0.y) GATH2(v0.z) GATH2(v0.w)
        GATH2(v1.x) GATH2(v1.y) GATH2(v1.z) GATH2(v1.w)
        #undef GATH2
        M0[j] = mx0 + q0;
        M1[j] = mx1 + q1;
        ls0 += sp0 + 16.f*q0;  lq0 += spp0 + 2.f*q0*sp0 + 16.f*q0*q0;
        ls1 += sp1 + 16.f*q1;  lq1 += spp1 + 2.f*q1*sp1 + 16.f*q1*q1;
    }
    rS0[threadIdx.x] = (double)ls0; rQ0[threadIdx.x] = (double)lq0;
    rS1[threadIdx.x] = (double)ls1; rQ1[threadIdx.x] = (double)lq1;
    __syncthreads();
    for (int s=128; s>0; s>>=1){
        if (threadIdx.x < s){
            rS0[threadIdx.x]+=rS0[threadIdx.x+s]; rQ0[threadIdx.x]+=rQ0[threadIdx.x+s];
            rS1[threadIdx.x]+=rS1[threadIdx.x+s]; rQ1[threadIdx.x]+=rQ1[threadIdx.x+s];
        }
        __syncthreads();
    }
    if (threadIdx.x==0){
        atomicAdd(&g_dsum[o0], rS0[0]);
        atomicAdd(&g_dsq[o0],  rQ0[0]);
        atomicAdd(&g_dsum[o1], rS1[0]);
        atomicAdd(&g_dsq[o1],  rQ1[0]);
    }
}

__global__ void k_zero(int O){
    int o = blockIdx.x*blockDim.x + threadIdx.x;
    if (o < O){ g_dsum[o]=0.0; g_dsq[o]=0.0; }
}

__global__ void k_finalize(int O, double inv){
    int o = blockIdx.x*blockDim.x + threadIdx.x;
    if (o < O){
        double mean = g_dsum[o]*inv;
        double var  = g_dsq[o]*inv - mean*mean;
        g_mean[o] = (float)mean;
        g_rstd[o] = (float)(1.0/sqrt(var + 1e-5));
    }
}

// BN + lrelu + bf16-pair emit
__global__ void k_bn_act(int srcsel, int dstsel, int dstp, int O){
    int t = blockIdx.x*blockDim.x + threadIdx.x;
    if (t >= (O>>1)*COLS) return;
    int op = t >> 13, col = t & 8191;
    const float* in = srcsel ? g_ypre : g_ymax;
    int o0 = 2*op, o1 = 2*op+1;
    float v0 = (in[(size_t)o0*COLS+col] - g_mean[o0]) * g_rstd[o0];
    v0 = (v0 > 0.f) ? v0 : 0.2f*v0;
    float v1 = (in[(size_t)o1*COLS+col] - g_mean[o1]) * g_rstd[o1];
    v1 = (v1 > 0.f) ? v1 : 0.2f*v1;
    unsigned h, l;
    split2(v0, v1, h, l);
    if (dstsel){
        g_HPH[(size_t)op*COLS+col] = h;
        g_HPL[(size_t)op*COLS+col] = l;
    } else {
        g_XPH[(size_t)(dstp+op)*COLS+col] = h;
        g_XPL[(size_t)(dstp+op)*COLS+col] = l;
    }
}

// global pooling from bf16 pairs, two channels per block
__global__ void k_pool(){   // grid (512, NB)
    __shared__ float sMx0[256], sSm0[256], sMx1[256], sSm1[256];
    int op = blockIdx.x, b = blockIdx.y;
    const unsigned* ph = g_HPH + (size_t)op*COLS + b*NPTS;
    const unsigned* pl = g_HPL + (size_t)op*COLS + b*NPTS;
    float mx0 = -1e30f, sm0 = 0.f, mx1 = -1e30f, sm1 = 0.f;
    for (int n = threadIdx.x; n < NPTS; n += 256){
        unsigned h = ph[n], l = pl[n];
        float v0 = __uint_as_float(h << 16) + __uint_as_float(l << 16);
        float v1 = __uint_as_float(h & 0xFFFF0000u) + __uint_as_float(l & 0xFFFF0000u);
        mx0 = fmaxf(mx0, v0); sm0 += v0;
        mx1 = fmaxf(mx1, v1); sm1 += v1;
    }
    sMx0[threadIdx.x]=mx0; sSm0[threadIdx.x]=sm0;
    sMx1[threadIdx.x]=mx1; sSm1[threadIdx.x]=sm1;
    __syncthreads();
    for (int s=128;s>0;s>>=1){
        if (threadIdx.x<s){
            sMx0[threadIdx.x]=fmaxf(sMx0[threadIdx.x],sMx0[threadIdx.x+s]); sSm0[threadIdx.x]+=sSm0[threadIdx.x+s];
            sMx1[threadIdx.x]=fmaxf(sMx1[threadIdx.x],sMx1[threadIdx.x+s]); sSm1[threadIdx.x]+=sSm1[threadIdx.x+s];
        }
        __syncthreads();
    }
    if (threadIdx.x==0){
        int o0 = 2*op, o1 = 2*op+1;
        g_g[b*2048 + o0] = sMx0[0];
        g_g[b*2048 + 1024 + o0] = sSm0[0]/2048.f;
        g_g[b*2048 + o1] = sMx1[0];
        g_g[b*2048 + 1024 + o1] = sSm1[0]/2048.f;
    }
}

// generic FC
__global__ void k_fc(const float* __restrict__ W, const float* __restrict__ bias,
                     int insel, int outsel, int F, int C, int mode){
    extern __shared__ float sIn[];
    const float* in = buf_ptr(insel);
    float* out = buf_ptr(outsel);
    for (int i = threadIdx.x; i < 4*C; i += blockDim.x) sIn[i] = in[i];
    __syncthreads();
    int warp = threadIdx.x >> 5, lane = threadIdx.x & 31;
    int warps = blockDim.x >> 5;
    int f = blockIdx.x*warps + warp;
    if (f >= F) return;
    float a0=0.f,a1=0.f,a2=0.f,a3=0.f;
    const float4* Wr = (const float4*)(W + (size_t)f*C);
    int C4 = C >> 2;
    for (int c4 = lane; c4 < C4; c4 += 32) {
        float4 w = Wr[c4];
        int c = c4 << 2;
        a0 += w.x*sIn[c]       + w.y*sIn[c+1]       + w.z*sIn[c+2]       + w.w*sIn[c+3];
        a1 += w.x*sIn[C+c]     + w.y*sIn[C+c+1]     + w.z*sIn[C+c+2]     + w.w*sIn[C+c+3];
        a2 += w.x*sIn[2*C+c]   + w.y*sIn[2*C+c+1]   + w.z*sIn[2*C+c+2]   + w.w*sIn[2*C+c+3];
        a3 += w.x*sIn[3*C+c]   + w.y*sIn[3*C+c+1]   + w.z*sIn[3*C+c+2]   + w.w*sIn[3*C+c+3];
    }
    #pragma unroll
    for (int s=16;s>0;s>>=1){
        a0 += __shfl_down_sync(0xffffffffu, a0, s);
        a1 += __shfl_down_sync(0xffffffffu, a1, s);
        a2 += __shfl_down_sync(0xffffffffu, a2, s);
        a3 += __shfl_down_sync(0xffffffffu, a3, s);
    }
    if (lane == 0){
        if (mode == 2){
            float m = 0.25f*(a0+a1+a2+a3);
            float d0=a0-m, d1=a1-m, d2=a2-m, d3=a3-m;
            float var = 0.25f*(d0*d0+d1*d1+d2*d2+d3*d3);
            float rs = rsqrtf(var + 1e-5f);
            float v;
            v=d0*rs; out[0*F+f] = (v>0.f)?v:0.2f*v;
            v=d1*rs; out[1*F+f] = (v>0.f)?v:0.2f*v;
            v=d2*rs; out[2*F+f] = (v>0.f)?v:0.2f*v;
            v=d3*rs; out[3*F+f] = (v>0.f)?v:0.2f*v;
        } else {
            float bb = bias ? bias[f] : 0.f;
            a0+=bb; a1+=bb; a2+=bb; a3+=bb;
            if (mode == 1){ a0=fmaxf(a0,0.f); a1=fmaxf(a1,0.f); a2=fmaxf(a2,0.f); a3=fmaxf(a3,0.f); }
            out[0*F+f]=a0; out[1*F+f]=a1; out[2*F+f]=a2; out[3*F+f]=a3;
        }
    }
}

__global__ void k_pc2xyz(const float* __restrict__ w, const float* __restrict__ bias){
    __shared__ float sw[192];
    int b = blockIdx.x, n = threadIdx.x;
    for (int i = threadIdx.x; i < 192; i += 128) sw[i] = w[i];
    __syncthreads();
    float a0 = bias[0], a1 = bias[1], a2 = bias[2];
    for (int c=0;c<64;c++){
        float f = g_pc2f[b*8192 + c*128 + n];
        a0 += sw[c]*f; a1 += sw[64+c]*f; a2 += sw[128+c]*f;
    }
    g_pc2xyz[b*384 + 0*128 + n] = a0;
    g_pc2xyz[b*384 + 1*128 + n] = a1;
    g_pc2xyz[b*384 + 2*128 + n] = a2;
}

__global__ void k_pc3tmp(const float* __restrict__ w1, const float* __restrict__ b1){
    int b = blockIdx.x, o = blockIdx.y, n = threadIdx.x;
    float acc = b1[o];
    const float* w = w1 + o*128;
    const float* f = g_pc3f + b*65536 + n;
    for (int c=0;c<128;c++) acc += w[c]*f[c*512];
    g_pc3tmp[(b*64+o)*512+n] = fmaxf(acc, 0.f);
}

__global__ void k_pc3xyz(const float* __restrict__ w2, const float* __restrict__ b2){
    __shared__ float sw[192];
    int b = blockIdx.x, n = threadIdx.x;
    for (int i = threadIdx.x; i < 192; i += 512) sw[i] = w2[i];
    __syncthreads();
    float a0 = b2[0], a1 = b2[1], a2 = b2[2];
    for (int o=0;o<64;o++){
        float t = g_pc3tmp[(b*64+o)*512+n];
        a0 += sw[o]*t; a1 += sw[64+o]*t; a2 += sw[128+o]*t;
    }
    g_pc3xyz[b*1536 + 0*512 + n] = a0;
    g_pc3xyz[b*1536 + 1*512 + n] = a1;
    g_pc3xyz[b*1536 + 2*512 + n] = a2;
}

__global__ void k_expand1(float* __restrict__ out){
    __shared__ float px[64], py[64], pz[64], pxx[64];
    int b = blockIdx.x, i = threadIdx.x;
    float vx = g_pc1[b*192 + 0*64 + i];
    float vy = g_pc1[b*192 + 1*64 + i];
    float vz = g_pc1[b*192 + 2*64 + i];
    px[i]=vx; py[i]=vy; pz[i]=vz; pxx[i]=vx*vx+vy*vy+vz*vz;
    __syncthreads();
    float cx=px[i], cy=py[i], cz=pz[i], cxx=pxx[i];
    float best=-1e30f; int bj=0;
    for (int j=0;j<64;j++){
        float pd = 2.f*(cx*px[j]+cy*py[j]+cz*pz[j]) - cxx - pxx[j];
        if (pd > best){ best=pd; bj=j; }
    }
    out[(b*64+i)*3+0]=cx; out[(b*64+i)*3+1]=cy; out[(b*64+i)*3+2]=cz;
    float* mid = out + 768;
    const float* p2 = g_pc2xyz + b*384;
    int n0 = 2*i, n1 = 2*i+1;
    float nx=px[bj], ny=py[bj], nz=pz[bj];
    mid[(b*128+n0)*3+0] = (2.f*cx - nx) + p2[0*128+n0];
    mid[(b*128+n0)*3+1] = (2.f*cy - ny) + p2[1*128+n0];
    mid[(b*128+n0)*3+2] = (2.f*cz - nz) + p2[2*128+n0];
    mid[(b*128+n1)*3+0] = cx + p2[0*128+n1];
    mid[(b*128+n1)*3+1] = cy + p2[1*128+n1];
    mid[(b*128+n1)*3+2] = cz + p2[2*128+n1];
}

__global__ void k_expand2(float* __restrict__ out){
    __shared__ float px[128], py[128], pz[128], pxx[128];
    int b = blockIdx.x, i = threadIdx.x;
    float vx = g_pc2xyz[b*384 + 0*128 + i];
    float vy = g_pc2xyz[b*384 + 1*128 + i];
    float vz = g_pc2xyz[b*384 + 2*128 + i];
    px[i]=vx; py[i]=vy; pz[i]=vz; pxx[i]=vx*vx+vy*vy+vz*vz;
    __syncthreads();
    float cx=px[i], cy=py[i], cz=pz[i], cxx=pxx[i];
    float pd0=-1e30f,pd1=-1e30f,pd2=-1e30f; int j0=0,j1=0,j2=0;
    for (int j=0;j<128;j++){
        float pd = 2.f*(cx*px[j]+cy*py[j]+cz*pz[j]) - cxx - pxx[j];
        if (pd > pd2){
            if (pd > pd1){
                pd2=pd1; j2=j1;
                if (pd > pd0){ pd1=pd0; j1=j0; pd0=pd; j0=j; }
                else { pd1=pd; j1=j; }
            } else { pd2=pd; j2=j; }
        }
    }
    float* hi = out + 2304;
    const float* p3 = g_pc3xyz + b*1536;
    int jn[3] = {j0, j1, j2};
    #pragma unroll
    for (int m=0;m<3;m++){
        int n = 4*i+m, j = jn[m];
        hi[(b*512+n)*3+0] = (2.f*cx - px[j]) + p3[0*512+n];
        hi[(b*512+n)*3+1] = (2.f*cy - py[j]) + p3[1*512+n];
        hi[(b*512+n)*3+2] = (2.f*cz - pz[j]) + p3[2*512+n];
    }
    int n = 4*i+3;
    hi[(b*512+n)*3+0] = cx + p3[0*512+n];
    hi[(b*512+n)*3+1] = cy + p3[1*512+n];
    hi[(b*512+n)*3+2] = cz + p3[2*512+n];
}

// ---------------- host ----------------

static const double INV_EDGE = 1.0/131072.0;
static const double INV_PW   = 1.0/8192.0;

#define WO2 512
#define WO3 2560
#define WO4 10752
#define SO21 0
#define SO31 8192
#define SO5  40960

extern "C" void kernel_launch(void* const* d_in, const int* in_sizes, int n_in,
                              void* d_out, int out_size) {
    const float* x         = (const float*)d_in[0];
    const float* conv1_w   = (const float*)d_in[1];
    const float* conv2_w   = (const float*)d_in[2];
    const float* conv2_1_w = (const float*)d_in[3];
    const float* conv3_w   = (const float*)d_in[4];
    const float* conv3_1_w = (const float*)d_in[5];
    const float* conv4_w   = (const float*)d_in[6];
    const float* conv5_w   = (const float*)d_in[7];
    const float* linear1_w = (const float*)d_in[8];
    const float* fc1_w = (const float*)d_in[9];   const float* fc1_b = (const float*)d_in[10];
    const float* fc2_w = (const float*)d_in[11];  const float* fc2_b = (const float*)d_in[12];
    const float* fc3_w = (const float*)d_in[13];  const float* fc3_b = (const float*)d_in[14];
    const float* fc1_1_w = (const float*)d_in[15]; const float* fc1_1_b = (const float*)d_in[16];
    const float* fc2_1_w = (const float*)d_in[17]; const float* fc2_1_b = (const float*)d_in[18];
    const float* fc3_1_w = (const float*)d_in[19]; const float* fc3_1_b = (const float*)d_in[20];
    const float* gc11_w = (const float*)d_in[21];  const float* gc11_b = (const float*)d_in[22];
    const float* gc12_w = (const float*)d_in[23];  const float* gc12_b = (const float*)d_in[24];
    const float* gc21_w = (const float*)d_in[25];  const float* gc21_b = (const float*)d_in[26];
    float* out = (float*)d_out;

    // 0. weight splits
    k_wsplit_dual<<<(64*32+255)/256, 256>>>(conv2_w, WO2, 64, 64, 32);
    k_wsplit_dual<<<(128*64+255)/256, 256>>>(conv3_w, WO3, 128, 128, 64);
    k_wsplit_dual<<<(512*128+255)/256, 256>>>(conv4_w, WO4, 512, 256, 128);
    k_wsplit_stats<<<(128*64+255)/256, 256>>>(conv2_1_w, SO21, 128, 128, 64);
    k_wsplit_stats<<<(256*128+255)/256, 256>>>(conv3_1_w, SO31, 256, 256, 128);
    k_wsplit_stats<<<(1024*384+255)/256, 256>>>(conv5_w, SO5, 1024, 768, 384);

    // 1. fused transpose+pairs, then KNN (4 threads/point, two-stage bitonic merge)
    k_xt<<<(8*COLS)/256, 256>>>(x);
    k_knn<<<dim3(NB, 32), 256>>>();

    // 2. conv1 (fused fp32 gemm+gather): C=3 -> O=64 -> X pairs [0,32)
    k_zero<<<1, 256>>>(64);
    k_gather1<<<dim3(32, NB), 256>>>(conv1_w);
    k_finalize<<<1, 256>>>(64, INV_EDGE);
    k_bn_act<<<(32*COLS)/256, 256>>>(0, 0, 0, 64);

    // 3. conv2 (edge): C=64 -> O=64 -> X pairs [32,64)
    k_zero<<<1, 256>>>(64);
    k_gemm_dual<<<dim3(COLS/128, 1), 256>>>(1, WO2, 64, 32);
    k_gather2<<<dim3(32, NB), 256>>>();
    k_finalize<<<1, 256>>>(64, INV_EDGE);
    k_bn_act<<<(32*COLS)/256, 256>>>(0, 0, 32, 64);

    // 4. conv2_1: K=128 -> O=128 -> H pairs
    k_zero<<<1, 256>>>(128);
    k_gemm_stats<<<dim3(COLS/128, 2), 256>>>(1, SO21, 128, 64);
    k_finalize<<<1, 256>>>(128, INV_PW);
    k_bn_act<<<(64*COLS)/256, 256>>>(1, 1, 0, 128);

    // 5. conv3 (edge): C=128 (h) -> O=128 -> X pairs [64,128)
    k_zero<<<1, 256>>>(128);
    k_gemm_dual<<<dim3(COLS/128, 2), 256>>>(2, WO3, 128, 64);
    k_gather2<<<dim3(64, NB), 256>>>();
    k_finalize<<<1, 256>>>(128, INV_EDGE);
    k_bn_act<<<(64*COLS)/256, 256>>>(0, 0, 64, 128);

    // 6. conv3_1: K=256 -> O=256 -> H pairs
    k_zero<<<1, 256>>>(256);
    k_gemm_stats<<<dim3(COLS/128, 4), 256>>>(1, SO31, 256, 128);
    k_finalize<<<1, 256>>>(256, INV_PW);
    k_bn_act<<<(128*COLS)/256, 256>>>(1, 1, 0, 256);

    // 7. conv4 (edge): C=256 (h) -> O=512 -> X pairs [128,384)
    k_zero<<<2, 256>>>(512);
    k_gemm_dual<<<dim3(COLS/128, 8), 256>>>(2, WO4, 256, 128);
    k_gather2<<<dim3(256, NB), 256>>>();
    k_finalize<<<2, 256>>>(512, INV_EDGE);
    k_bn_act<<<(256*COLS)/256, 256>>>(0, 0, 128, 512);

    // 8. conv5: K=768 -> O=1024 -> H pairs
    k_zero<<<4, 256>>>(1024);
    k_gemm_stats<<<dim3(COLS/128, 16), 256>>>(1, SO5, 768, 384);
    k_finalize<<<4, 256>>>(1024, INV_PW);
    k_bn_act<<<(512*COLS)/256, 256>>>(1, 1, 0, 1024);

    // 9. global pooling from pairs
    k_pool<<<dim3(512, NB), 256>>>();

    // 10-12. fc chain + heads
    k_fc<<<2048/8, 256, 4*2048*4>>>(linear1_w, nullptr, 0, 1, 2048, 2048, 2);
    k_fc<<<1024/8, 256, 4*2048*4>>>(fc1_w, fc1_b, 1, 2, 1024, 2048, 1);
    k_fc<<<512/8, 256, 4*1024*4>>>(fc2_w, fc2_b, 2, 3, 512, 1024, 1);
    k_fc<<<256/8, 256, 4*512*4>>>(fc3_w, fc3_b, 3, 4, 256, 512, 1);
    k_fc<<<192/8, 256, 4*256*4>>>(fc3_1_w, fc3_1_b, 4, 5, 192, 256, 0);
    k_fc<<<8192/32, 1024, 4*512*4>>>(fc2_1_w, fc2_1_b, 3, 6, 8192, 512, 1);
    k_fc<<<65536/32, 1024, 4*1024*4>>>(fc1_1_w, fc1_1_b, 2, 7, 65536, 1024, 1);

    // 13. small convs
    k_pc2xyz<<<NB, 128>>>(gc21_w, gc21_b);
    k_pc3tmp<<<dim3(NB, 64), 512>>>(gc11_w, gc11_b);
    k_pc3xyz<<<NB, 512>>>(gc12_w, gc12_b);

    // 14. mirror expansions + final outputs
    k_expand1<<<NB, 64>>>(out);
    k_expand2<<<NB, 128>>>(out);
}

// round 16
// speedup vs baseline: 1.2664x; 1.0149x over previous
#include <cuda_runtime.h>
#include <cuda_bf16.h>
#include <math.h>

#define COLS 8192   // B*N
#define NPTS 2048
#define NB 4
#define KNB 16

// ---------------- static device scratch ----------------
__device__ float g_xt[3*COLS];
__device__ unsigned short g_idx[COLS*KNB];
__device__ float g_P[512*COLS];
__device__ float g_Q[512*COLS];
__device__ float g_ymax[512*COLS];
__device__ float g_ypre[1024*COLS];
__device__ float g_mean[1024];
__device__ float g_rstd[1024];
__device__ double g_dsum[1024];
__device__ double g_dsq[1024];
// pair-packed bf16 activations (u32 = bf16(k_even) | bf16(k_odd)<<16)
__device__ unsigned g_TPH[8*COLS],   g_TPL[8*COLS];
__device__ unsigned g_XPH[384*COLS], g_XPL[384*COLS];
__device__ unsigned g_HPH[512*COLS], g_HPL[512*COLS];
// pair-packed bf16 weights
__device__ unsigned g_W1H[76288], g_W1L[76288], g_W2H[76288], g_W2L[76288];
__device__ unsigned g_WSH[434176], g_WSL[434176];
// tail buffers
__device__ float g_g[NB*2048];
__device__ float g_lat[NB*2048];
__device__ float g_x1v[NB*1024];
__device__ float g_x2v[NB*512];
__device__ float g_x3v[NB*256];
__device__ float g_pc1[NB*192];
__device__ float g_pc2f[NB*8192];
__device__ float g_pc2xyz[NB*384];
__device__ float g_pc3f[NB*65536];
__device__ float g_pc3tmp[NB*64*512];
__device__ float g_pc3xyz[NB*1536];

__device__ __forceinline__ const unsigned* xpH(int s){ return s==0? g_TPH : (s==1? g_XPH : g_HPH); }
__device__ __forceinline__ const unsigned* xpL(int s){ return s==0? g_TPL : (s==1? g_XPL : g_HPL); }
__device__ __forceinline__ float* buf_ptr(int s) {
    switch (s) {
        case 0: return g_g;    case 1: return g_lat;
        case 2: return g_x1v;  case 3: return g_x2v;
        case 4: return g_x3v;  case 5: return g_pc1;
        case 6: return g_pc2f; case 7: return g_pc3f;
    }
    return g_g;
}

// ---- helpers ----
__device__ __forceinline__ void split_bf16(float v, unsigned short &h, unsigned short &l){
    __nv_bfloat16 bh = __float2bfloat16_rn(v);
    float r = v - __bfloat162float(bh);
    __nv_bfloat16 bl = __float2bfloat16_rn(r);
    h = *(unsigned short*)&bh;
    l = *(unsigned short*)&bl;
}
__device__ __forceinline__ void split2(float a, float b, unsigned &h, unsigned &l){
    unsigned short ah,al,bh,bl;
    split_bf16(a, ah, al);
    split_bf16(b, bh, bl);
    h = (unsigned)ah | ((unsigned)bh << 16);
    l = (unsigned)al | ((unsigned)bl << 16);
}
__device__ __forceinline__ void mma16816(float* c, unsigned a0, unsigned a1, unsigned a2, unsigned a3,
                                         unsigned b0, unsigned b1){
    asm volatile(
        "mma.sync.aligned.m16n8k16.row.col.f32.bf16.bf16.f32 "
        "{%0,%1,%2,%3}, {%4,%5,%6,%7}, {%8,%9}, {%0,%1,%2,%3};"
        : "+f"(c[0]), "+f"(c[1]), "+f"(c[2]), "+f"(c[3])
        : "r"(a0), "r"(a1), "r"(a2), "r"(a3), "r"(b0), "r"(b1));
}
__device__ __forceinline__ unsigned smaddr(const void* p){
    return (unsigned)__cvta_generic_to_shared(p);
}
__device__ __forceinline__ void cp16(unsigned dst, const void* src){
    asm volatile("cp.async.ca.shared.global [%0], [%1], 16;" :: "r"(dst), "l"(src));
}

// ---------------- kernels ----------------

// fused transpose + xt bf16 pairs
__global__ void k_xt(const float* __restrict__ x) {
    int t = blockIdx.x*blockDim.x + threadIdx.x;
    if (t >= 8*COLS) return;
    int pr = t >> 13, col = t & 8191;
    int b = col >> 11, n = col & 2047;
    int c0 = 2*pr, c1 = 2*pr+1;
    float v0 = (c0 < 3) ? x[(b*NPTS+n)*3 + c0] : 0.f;
    float v1 = (c1 < 3) ? x[(b*NPTS+n)*3 + c1] : 0.f;
    if (c0 < 3) g_xt[c0*COLS + col] = v0;
    if (c1 < 3) g_xt[c1*COLS + col] = v1;
    unsigned h, l;
    split2(v0, v1, h, l);
    g_TPH[t] = h; g_TPL[t] = l;
}

__global__ void k_wsplit_dual(const float* __restrict__ W, int woff, int O, int K, int ldp){
    int t = blockIdx.x*blockDim.x + threadIdx.x;
    if (t >= O*ldp) return;
    int o = t / ldp, kp = t - o*ldp;
    int kk = 2*kp;
    float w1a = 0.f, w1b = 0.f, w2a = 0.f, w2b = 0.f;
    if (kk < K){
        w1a = W[(size_t)o*2*K + kk];
        w2a = W[(size_t)o*2*K + K + kk] - w1a;
    }
    if (kk+1 < K){
        w1b = W[(size_t)o*2*K + kk+1];
        w2b = W[(size_t)o*2*K + K + kk+1] - w1b;
    }
    unsigned h, l;
    split2(w1a, w1b, h, l); g_W1H[woff+t] = h; g_W1L[woff+t] = l;
    split2(w2a, w2b, h, l); g_W2H[woff+t] = h; g_W2L[woff+t] = l;
}

__global__ void k_wsplit_stats(const float* __restrict__ W, int woff, int O, int K, int ldp){
    int t = blockIdx.x*blockDim.x + threadIdx.x;
    if (t >= O*ldp) return;
    int o = t / ldp, kp = t - o*ldp;
    int kk = 2*kp;
    float wa = (kk   < K) ? W[(size_t)o*K + kk]   : 0.f;
    float wb = (kk+1 < K) ? W[(size_t)o*K + kk+1] : 0.f;
    unsigned h, l;
    split2(wa, wb, h, l); g_WSH[woff+t] = h; g_WSL[woff+t] = l;
}

// KNN k=16: 8 threads per point, each scans 256 candidates; three-stage
// bitonic-selection merge via shuffles with tie-aware (stable) ordering.
// Comparator everywhere: higher pd first; equal pd -> lower index first.
__global__ void k_knn() {   // grid (NB, 64), 256 threads (32 points/block)
    __shared__ float sx[NPTS], sy[NPTS], sz[NPTS], sxx[NPTS];
    int b = blockIdx.x;
    for (int j = threadIdx.x; j < NPTS; j += 256) {
        float vx = g_xt[0*COLS + b*NPTS + j];
        float vy = g_xt[1*COLS + b*NPTS + j];
        float vz = g_xt[2*COLS + b*NPTS + j];
        sx[j]=vx; sy[j]=vy; sz[j]=vz; sxx[j]=vx*vx+vy*vy+vz*vz;
    }
    __syncthreads();
    int pi = blockIdx.y*32 + (threadIdx.x >> 3);
    int q = threadIdx.x & 7;
    float cx=sx[pi], cy=sy[pi], cz=sz[pi], cxx=sxx[pi];
    float pdk[KNB]; int idk[KNB];
    #pragma unroll
    for (int m=0;m<KNB;m++){ pdk[m]=-1e30f; idk[m]=0x7FFFFFFF; }
    int j0 = q << 8;
    for (int jj=0; jj<256; jj++){
        int j = j0 + jj;
        float pd = 2.f*(cx*sx[j]+cy*sy[j]+cz*sz[j]) - cxx - sxx[j];
        if (pd > pdk[KNB-1]) {
            pdk[KNB-1]=pd; idk[KNB-1]=j;
            #pragma unroll
            for (int m=KNB-1;m>0;m--){
                bool sw = pdk[m] > pdk[m-1];
                float tp = sw ? pdk[m-1] : pdk[m];
                int   ti = sw ? idk[m-1] : idk[m];
                pdk[m-1] = sw ? pdk[m] : pdk[m-1];
                idk[m-1] = sw ? idk[m] : idk[m-1];
                pdk[m] = tp; idk[m] = ti;
            }
        }
    }
    // merge helper macros (selection + stable bitonic cleanup)
    #define SEL_MERGE(SRCD, SRCI, DSTD, DSTI, XMASK, LOWBIT) { \
        bool lowg = (q & (LOWBIT)) == 0; \
        _Pragma("unroll") \
        for (int m=0;m<KNB;m++){ \
            float opd = __shfl_xor_sync(0xffffffffu, SRCD[KNB-1-m], (XMASK)); \
            int   oid = __shfl_xor_sync(0xffffffffu, SRCI[KNB-1-m], (XMASK)); \
            bool takeOwn = lowg ? (SRCD[m] >= opd) : (SRCD[m] > opd); \
            DSTD[m] = takeOwn ? SRCD[m] : opd; \
            DSTI[m] = takeOwn ? SRCI[m] : oid; \
        } }
    #define CLEANUP(DD, II) { \
        _Pragma("unroll") \
        for (int d = 8; d > 0; d >>= 1){ \
            _Pragma("unroll") \
            for (int i = 0; i < KNB; i++){ \
                if ((i & d) == 0){ \
                    bool sw = (DD[i] < DD[i+d]) || (DD[i] == DD[i+d] && II[i] > II[i+d]); \
                    float tp = sw ? DD[i] : DD[i+d]; \
                    int   ti = sw ? II[i] : II[i+d]; \
                    DD[i]   = sw ? DD[i+d] : DD[i]; \
                    II[i]   = sw ? II[i+d] : II[i]; \
                    DD[i+d] = tp; II[i+d] = ti; \
                } \
            } \
        } }
    float pd1[KNB]; int id1[KNB];
    SEL_MERGE(pdk, idk, pd1, id1, 1, 1)
    CLEANUP(pd1, id1)
    float pd2[KNB]; int id2[KNB];
    SEL_MERGE(pd1, id1, pd2, id2, 2, 2)
    CLEANUP(pd2, id2)
    int res[KNB];
    {
        bool lowg = (q & 4) == 0;
        #pragma unroll
        for (int m=0;m<KNB;m++){
            float opd = __shfl_xor_sync(0xffffffffu, pd2[KNB-1-m], 4);
            int   oid = __shfl_xor_sync(0xffffffffu, id2[KNB-1-m], 4);
            bool takeOwn = lowg ? (pd2[m] >= opd) : (pd2[m] > opd);
            res[m] = takeOwn ? id2[m] : oid;
        }
    }
    #undef SEL_MERGE
    #undef CLEANUP
    if (q == 0){
        #pragma unroll
        for (int m=0;m<KNB;m++)
            g_idx[(b*NPTS+pi)*KNB+m] = (unsigned short)res[m];
    }
}

// ---- tensor-core GEMMs: 64(M) x 128(N), cp.async double-buffered ----

__global__ void __launch_bounds__(256, 2)
k_gemm_dual(int xsel, int woff, int Kp, int ldp) {
    __shared__ unsigned sA1h[2][64][12], sA1l[2][64][12], sA2h[2][64][12], sA2l[2][64][12];
    __shared__ unsigned sBh[2][8][136], sBl[2][8][136];
    const unsigned* XH = xpH(xsel);
    const unsigned* XL = xpL(xsel);
    int tid = threadIdx.x;
    int warp = tid >> 5, lane = tid & 31;
    int mw = warp >> 1, nw = warp & 1;
    int gid = lane >> 2, qid = lane & 3;
    int o0 = blockIdx.y*64, n0 = blockIdx.x*128;
    int arow = (tid & 127) >> 1, ahalf = tid & 1;
    int bpr = tid >> 5, bc4 = tid & 31;
    bool hiA = (tid < 128);

    float accP[8][4], accQ[8][4];
    #pragma unroll
    for (int nt=0;nt<8;nt++)
        #pragma unroll
        for (int e=0;e<4;e++){ accP[nt][e]=0.f; accQ[nt][e]=0.f; }

    auto load_chunk = [&](int kp0, int buf){
        size_t aoff = (size_t)(woff + (o0 + arow)*ldp + kp0 + ahalf*4);
        unsigned adst = (arow*12 + ahalf*4)*4;
        if (hiA){
            cp16(smaddr(&sA1h[buf][0][0]) + adst, (const void*)(g_W1H + aoff));
            cp16(smaddr(&sA2h[buf][0][0]) + adst, (const void*)(g_W2H + aoff));
        } else {
            cp16(smaddr(&sA1l[buf][0][0]) + adst, (const void*)(g_W1L + aoff));
            cp16(smaddr(&sA2l[buf][0][0]) + adst, (const void*)(g_W2L + aoff));
        }
        size_t boff = (size_t)(kp0 + bpr)*COLS + n0 + bc4*4;
        unsigned bdst = (bpr*136 + bc4*4)*4;
        cp16(smaddr(&sBh[buf][0][0]) + bdst, (const void*)(XH + boff));
        cp16(smaddr(&sBl[buf][0][0]) + bdst, (const void*)(XL + boff));
    };

    int nch = Kp >> 4;
    load_chunk(0, 0);
    asm volatile("cp.async.commit_group;");
    for (int i = 0; i < nch; i++){
        int buf = i & 1;
        if (i + 1 < nch){
            load_chunk((i+1) << 3, (i+1) & 1);
            asm volatile("cp.async.commit_group;");
            asm volatile("cp.async.wait_group 1;");
        } else {
            asm volatile("cp.async.wait_group 0;");
        }
        __syncthreads();
        int rA = mw*16 + gid;
        unsigned a1h0=sA1h[buf][rA][qid], a1h1=sA1h[buf][rA+8][qid], a1h2=sA1h[buf][rA][qid+4], a1h3=sA1h[buf][rA+8][qid+4];
        unsigned a1l0=sA1l[buf][rA][qid], a1l1=sA1l[buf][rA+8][qid], a1l2=sA1l[buf][rA][qid+4], a1l3=sA1l[buf][rA+8][qid+4];
        unsigned a2h0=sA2h[buf][rA][qid], a2h1=sA2h[buf][rA+8][qid], a2h2=sA2h[buf][rA][qid+4], a2h3=sA2h[buf][rA+8][qid+4];
        unsigned a2l0=sA2l[buf][rA][qid], a2l1=sA2l[buf][rA+8][qid], a2l2=sA2l[buf][rA][qid+4], a2l3=sA2l[buf][rA+8][qid+4];
        #pragma unroll
        for (int nt=0;nt<8;nt++){
            int nc = nw*64 + nt*8 + gid;
            unsigned bh0 = sBh[buf][qid][nc], bh1 = sBh[buf][qid+4][nc];
            unsigned bl0 = sBl[buf][qid][nc], bl1 = sBl[buf][qid+4][nc];
            mma16816(accP[nt], a1h0,a1h1,a1h2,a1h3, bh0,bh1);
            mma16816(accP[nt], a1l0,a1l1,a1l2,a1l3, bh0,bh1);
            mma16816(accP[nt], a1h0,a1h1,a1h2,a1h3, bl0,bl1);
            mma16816(accQ[nt], a2h0,a2h1,a2h2,a2h3, bh0,bh1);
            mma16816(accQ[nt], a2l0,a2l1,a2l2,a2l3, bh0,bh1);
            mma16816(accQ[nt], a2h0,a2h1,a2h2,a2h3, bl0,bl1);
        }
        __syncthreads();
    }
    int r0 = o0 + mw*16 + gid, r1 = r0 + 8;
    #pragma unroll
    for (int nt=0;nt<8;nt++){
        int col = n0 + nw*64 + nt*8 + 2*qid;
        *(float2*)&g_P[(size_t)r0*COLS + col] = make_float2(accP[nt][0], accP[nt][1]);
        *(float2*)&g_P[(size_t)r1*COLS + col] = make_float2(accP[nt][2], accP[nt][3]);
        *(float2*)&g_Q[(size_t)r0*COLS + col] = make_float2(accQ[nt][0], accQ[nt][1]);
        *(float2*)&g_Q[(size_t)r1*COLS + col] = make_float2(accQ[nt][2], accQ[nt][3]);
    }
}

__global__ void __launch_bounds__(256, 2)
k_gemm_stats(int xsel, int woff, int Kp, int ldp) {
    __shared__ unsigned sAh[2][64][12], sAl[2][64][12];
    __shared__ unsigned sBh[2][8][136], sBl[2][8][136];
    __shared__ float sSum[64], sSq[64];
    const unsigned* XH = xpH(xsel);
    const unsigned* XL = xpL(xsel);
    int tid = threadIdx.x;
    int warp = tid >> 5, lane = tid & 31;
    int mw = warp >> 1, nw = warp & 1;
    int gid = lane >> 2, qid = lane & 3;
    int o0 = blockIdx.y*64, n0 = blockIdx.x*128;
    int arow = (tid & 127) >> 1, ahalf = tid & 1;
    int bpr = tid >> 5, bc4 = tid & 31;
    bool hiA = (tid < 128);

    float acc[8][4];
    #pragma unroll
    for (int nt=0;nt<8;nt++)
        #pragma unroll
        for (int e=0;e<4;e++) acc[nt][e]=0.f;

    auto load_chunk = [&](int kp0, int buf){
        size_t aoff = (size_t)(woff + (o0 + arow)*ldp + kp0 + ahalf*4);
        unsigned adst = (arow*12 + ahalf*4)*4;
        if (hiA) cp16(smaddr(&sAh[buf][0][0]) + adst, (const void*)(g_WSH + aoff));
        else     cp16(smaddr(&sAl[buf][0][0]) + adst, (const void*)(g_WSL + aoff));
        size_t boff = (size_t)(kp0 + bpr)*COLS + n0 + bc4*4;
        unsigned bdst = (bpr*136 + bc4*4)*4;
        cp16(smaddr(&sBh[buf][0][0]) + bdst, (const void*)(XH + boff));
        cp16(smaddr(&sBl[buf][0][0]) + bdst, (const void*)(XL + boff));
    };

    int nch = Kp >> 4;
    load_chunk(0, 0);
    asm volatile("cp.async.commit_group;");
    for (int i = 0; i < nch; i++){
        int buf = i & 1;
        if (i + 1 < nch){
            load_chunk((i+1) << 3, (i+1) & 1);
            asm volatile("cp.async.commit_group;");
            asm volatile("cp.async.wait_group 1;");
        } else {
            asm volatile("cp.async.wait_group 0;");
        }
        __syncthreads();
        int rA = mw*16 + gid;
        unsigned ah0=sAh[buf][rA][qid], ah1=sAh[buf][rA+8][qid], ah2=sAh[buf][rA][qid+4], ah3=sAh[buf][rA+8][qid+4];
        unsigned al0=sAl[buf][rA][qid], al1=sAl[buf][rA+8][qid], al2=sAl[buf][rA][qid+4], al3=sAl[buf][rA+8][qid+4];
        #pragma unroll
        for (int nt=0;nt<8;nt++){
            int nc = nw*64 + nt*8 + gid;
            unsigned bh0 = sBh[buf][qid][nc], bh1 = sBh[buf][qid+4][nc];
            unsigned bl0 = sBl[buf][qid][nc], bl1 = sBl[buf][qid+4][nc];
            mma16816(acc[nt], ah0,ah1,ah2,ah3, bh0,bh1);
            mma16816(acc[nt], al0,al1,al2,al3, bh0,bh1);
            mma16816(acc[nt], ah0,ah1,ah2,ah3, bl0,bl1);
        }
        __syncthreads();
    }
    if (tid < 64) { sSum[tid]=0.f; sSq[tid]=0.f; }
    __syncthreads();
    int lr0 = mw*16 + gid, lr1 = lr0 + 8;
    int r0 = o0 + lr0, r1 = o0 + lr1;
    float s0=0.f,q0=0.f,s1=0.f,q1=0.f;
    #pragma unroll
    for (int nt=0;nt<8;nt++){
        int col = n0 + nw*64 + nt*8 + 2*qid;
        float c0=acc[nt][0], c1=acc[nt][1], c2=acc[nt][2], c3=acc[nt][3];
        s0 += c0+c1; q0 += c0*c0+c1*c1;
        s1 += c2+c3; q1 += c2*c2+c3*c3;
        *(float2*)&g_ypre[(size_t)r0*COLS + col] = make_float2(c0, c1);
        *(float2*)&g_ypre[(size_t)r1*COLS + col] = make_float2(c2, c3);
    }
    atomicAdd(&sSum[lr0], s0); atomicAdd(&sSq[lr0], q0);
    atomicAdd(&sSum[lr1], s1); atomicAdd(&sSq[lr1], q1);
    __syncthreads();
    if (tid < 64) {
        atomicAdd(&g_dsum[o0+tid], (double)sSum[tid]);
        atomicAdd(&g_dsq[o0+tid],  (double)sSq[tid]);
    }
}

// conv1 fused gemm+gather (fp32 exact)
__global__ void __launch_bounds__(256) k_gather1(const float* __restrict__ W){  // grid (32, NB)
    __shared__ float s0[NPTS], s1[NPTS], s2[NPTS];
    __shared__ float sP0[NPTS], sP1[NPTS];
    int op = blockIdx.x, b = blockIdx.y;
    int o0 = 2*op, o1 = o0 + 1;
    for (int j = threadIdx.x; j < NPTS; j += 256){
        s0[j] = g_xt[0*COLS + b*NPTS + j];
        s1[j] = g_xt[1*COLS + b*NPTS + j];
        s2[j] = g_xt[2*COLS + b*NPTS + j];
    }
    __syncthreads();
    float w10=W[o0*6], w11=W[o0*6+1], w12=W[o0*6+2];
    float v20=W[o0*6+3]-w10, v21=W[o0*6+4]-w11, v22=W[o0*6+5]-w12;
    float u10=W[o1*6], u11=W[o1*6+1], u12=W[o1*6+2];
    float t20=W[o1*6+3]-u10, t21=W[o1*6+4]-u11, t22=W[o1*6+5]-u12;
    for (int j = threadIdx.x; j < NPTS; j += 256){
        sP0[j] = w10*s0[j] + w11*s1[j] + w12*s2[j];
        sP1[j] = u10*s0[j] + u11*s1[j] + u12*s2[j];
    }
    __syncthreads();
    float ls0=0.f, lq0=0.f, ls1=0.f, lq1=0.f;
    float* M0 = g_ymax + (size_t)o0*COLS + b*NPTS;
    float* M1 = g_ymax + (size_t)o1*COLS + b*NPTS;
    for (int j = threadIdx.x; j < NPTS; j += 256){
        float q0 = v20*s0[j] + v21*s1[j] + v22*s2[j];
        float q1 = t20*s0[j] + t21*s1[j] + t22*s2[j];
        const uint4* ip = (const uint4*)(g_idx + (size_t)(b*NPTS+j)*KNB);
        uint4 v0 = ip[0], v1 = ip[1];
        float sp0=0.f, spp0=0.f, mx0=-1e30f;
        float sp1=0.f, spp1=0.f, mx1=-1e30f;
        #define GATH2(u) { \
            unsigned i0 = (u) & 0xFFFFu, i1 = (u) >> 16; \
            float p0 = sP0[i0], p1 = sP0[i1]; \
            sp0 += p0 + p1; spp0 = fmaf(p0,p0,fmaf(p1,p1,spp0)); \
            mx0 = fmaxf(mx0, fmaxf(p0, p1)); \
            float r0 = sP1[i0], r1 = sP1[i1]; \
            sp1 += r0 + r1; spp1 = fmaf(r0,r0,fmaf(r1,r1,spp1)); \
            mx1 = fmaxf(mx1, fmaxf(r0, r1)); }
        GATH2(v0.x) GATH2(v0.y) GATH2(v0.z) GATH2(v0.w)
        GATH2(v1.x) GATH2(v1.y) GATH2(v1.z) GATH2(v1.w)
        #undef GATH2
        M0[j] = mx0 + q0;
        M1[j] = mx1 + q1;
        ls0 += sp0 + 16.f*q0;  lq0 += spp0 + 2.f*q0*sp0 + 16.f*q0*q0;
        ls1 += sp1 + 16.f*q1;  lq1 += spp1 + 2.f*q1*sp1 + 16.f*q1*q1;
    }
    double d0=(double)ls0, e0=(double)lq0, d1=(double)ls1, e1=(double)lq1;
    #pragma unroll
    for (int s=16;s>0;s>>=1){
        d0 += __shfl_down_sync(0xffffffffu, d0, s);
        e0 += __shfl_down_sync(0xffffffffu, e0, s);
        d1 += __shfl_down_sync(0xffffffffu, d1, s);
        e1 += __shfl_down_sync(0xffffffffu, e1, s);
    }
    if ((threadIdx.x & 31) == 0){
        atomicAdd(&g_dsum[o0], d0);
        atomicAdd(&g_dsq[o0],  e0);
        atomicAdd(&g_dsum[o1], d1);
        atomicAdd(&g_dsq[o1],  e1);
    }
}

// gather-max for two channels, Q-factorized
__global__ void k_gather2() {   // grid (O/2, NB), 256 threads
    __shared__ float sP0[NPTS], sP1[NPTS];
    __shared__ double rS0[256], rQ0[256], rS1[256], rQ1[256];
    int op = blockIdx.x, b = blockIdx.y;
    int o0 = 2*op, o1 = o0 + 1;
    size_t base0 = (size_t)o0*COLS + b*NPTS;
    size_t base1 = (size_t)o1*COLS + b*NPTS;
    const float* P0 = g_P + base0;
    const float* P1 = g_P + base1;
    for (int j = threadIdx.x; j < NPTS; j += 256){ sP0[j] = P0[j]; sP1[j] = P1[j]; }
    __syncthreads();
    float ls0 = 0.f, lq0 = 0.f, ls1 = 0.f, lq1 = 0.f;
    const float* Q0 = g_Q + base0;
    const float* Q1 = g_Q + base1;
    float* M0 = g_ymax + base0;
    float* M1 = g_ymax + base1;
    for (int j = threadIdx.x; j < NPTS; j += 256) {
        float q0 = Q0[j], q1 = Q1[j];
        const uint4* ip = (const uint4*)(g_idx + (size_t)(b*NPTS+j)*KNB);
        uint4 v0 = ip[0], v1 = ip[1];
        float sp0=0.f, spp0=0.f, mx0=-1e30f;
        float sp1=0.f, spp1=0.f, mx1=-1e30f;
        #define GATH2(u) { \
            unsigned i0 = (u) & 0xFFFFu, i1 = (u) >> 16; \
            float p0 = sP0[i0], p1 = sP0[i1]; \
            sp0 += p0 + p1; spp0 = fmaf(p0,p0,fmaf(p1,p1,spp0)); \
            mx0 = fmaxf(mx0, fmaxf(p0, p1)); \
            float r0 = sP1[i0], r1 = sP1[i1]; \
            sp1 += r0 + r1; spp1 = fmaf(r0,r0,fmaf(r1,r1,spp1)); \
            mx1 = fmaxf(mx1, fmaxf(r0, r1)); }
        GATH2(v0.x) GATH2(v0.y) GATH2(v0.z) GATH2(v0.w)
        GATH2(v1.x) GATH2(v1.y) GATH2(v1.z) GATH2(v1.w)
        #undef GATH2
        M0[j] = mx0 + q0;
        M1[j] = mx1 + q1;
        ls0 += sp0 + 16.f*q0;  lq0 += spp0 + 2.f*q0*sp0 + 16.f*q0*q0;
        ls1 += sp1 + 16.f*q1;  lq1 += spp1 + 2.f*q1*sp1 + 16.f*q1*q1;
    }
    rS0[threadIdx.x] = (double)ls0; rQ0[threadIdx.x] = (double)lq0;
    rS1[threadIdx.x] = (double)ls1; rQ1[threadIdx.x] = (double)lq1;
    __syncthreads();
    for (int s=128; s>0; s>>=1){
        if (threadIdx.x < s){
            rS0[threadIdx.x]+=rS0[threadIdx.x+s]; rQ0[threadIdx.x]+=rQ0[threadIdx.x+s];
            rS1[threadIdx.x]+=rS1[threadIdx.x+s]; rQ1[threadIdx.x]+=rQ1[threadIdx.x+s];
        }
        __syncthreads();
    }
    if (threadIdx.x==0){
        atomicAdd(&g_dsum[o0], rS0[0]);
        atomicAdd(&g_dsq[o0],  rQ0[0]);
        atomicAdd(&g_dsum[o1], rS1[0]);
        atomicAdd(&g_dsq[o1],  rQ1[0]);
    }
}

__global__ void k_zero(int O){
    int o = blockIdx.x*blockDim.x + threadIdx.x;
    if (o < O){ g_dsum[o]=0.0; g_dsq[o]=0.0; }
}

__global__ void k_finalize(int O, double inv){
    int o = blockIdx.x*blockDim.x + threadIdx.x;
    if (o < O){
        double mean = g_dsum[o]*inv;
        double var  = g_dsq[o]*inv - mean*mean;
        g_mean[o] = (float)mean;
        g_rstd[o] = (float)(1.0/sqrt(var + 1e-5));
    }
}

// BN + lrelu + bf16-pair emit
__global__ void k_bn_act(int srcsel, int dstsel, int dstp, int O){
    int t = blockIdx.x*blockDim.x + threadIdx.x;
    if (t >= (O>>1)*COLS) return;
    int op = t >> 13, col = t & 8191;
    const float* in = srcsel ? g_ypre : g_ymax;
    int o0 = 2*op, o1 = 2*op+1;
    float v0 = (in[(size_t)o0*COLS+col] - g_mean[o0]) * g_rstd[o0];
    v0 = (v0 > 0.f) ? v0 : 0.2f*v0;
    float v1 = (in[(size_t)o1*COLS+col] - g_mean[o1]) * g_rstd[o1];
    v1 = (v1 > 0.f) ? v1 : 0.2f*v1;
    unsigned h, l;
    split2(v0, v1, h, l);
    if (dstsel){
        g_HPH[(size_t)op*COLS+col] = h;
        g_HPL[(size_t)op*COLS+col] = l;
    } else {
        g_XPH[(size_t)(dstp+op)*COLS+col] = h;
        g_XPL[(size_t)(dstp+op)*COLS+col] = l;
    }
}

// global pooling from bf16 pairs, two channels per block
__global__ void k_pool(){   // grid (512, NB)
    __shared__ float sMx0[256], sSm0[256], sMx1[256], sSm1[256];
    int op = blockIdx.x, b = blockIdx.y;
    const unsigned* ph = g_HPH + (size_t)op*COLS + b*NPTS;
    const unsigned* pl = g_HPL + (size_t)op*COLS + b*NPTS;
    float mx0 = -1e30f, sm0 = 0.f, mx1 = -1e30f, sm1 = 0.f;
    for (int n = threadIdx.x; n < NPTS; n += 256){
        unsigned h = ph[n], l = pl[n];
        float v0 = __uint_as_float(h << 16) + __uint_as_float(l << 16);
        float v1 = __uint_as_float(h & 0xFFFF0000u) + __uint_as_float(l & 0xFFFF0000u);
        mx0 = fmaxf(mx0, v0); sm0 += v0;
        mx1 = fmaxf(mx1, v1); sm1 += v1;
    }
    sMx0[threadIdx.x]=mx0; sSm0[threadIdx.x]=sm0;
    sMx1[threadIdx.x]=mx1; sSm1[threadIdx.x]=sm1;
    __syncthreads();
    for (int s=128;s>0;s>>=1){
        if (threadIdx.x<s){
            sMx0[threadIdx.x]=fmaxf(sMx0[threadIdx.x],sMx0[threadIdx.x+s]); sSm0[threadIdx.x]+=sSm0[threadIdx.x+s];
            sMx1[threadIdx.x]=fmaxf(sMx1[threadIdx.x],sMx1[threadIdx.x+s]); sSm1[threadIdx.x]+=sSm1[threadIdx.x+s];
        }
        __syncthreads();
    }
    if (threadIdx.x==0){
        int o0 = 2*op, o1 = 2*op+1;
        g_g[b*2048 + o0] = sMx0[0];
        g_g[b*2048 + 1024 + o0] = sSm0[0]/2048.f;
        g_g[b*2048 + o1] = sMx1[0];
        g_g[b*2048 + 1024 + o1] = sSm1[0]/2048.f;
    }
}

// generic FC
__global__ void k_fc(const float* __restrict__ W, const float* __restrict__ bias,
                     int insel, int outsel, int F, int C, int mode){
    extern __shared__ float sIn[];
    const float* in = buf_ptr(insel);
    float* out = buf_ptr(outsel);
    for (int i = threadIdx.x; i < 4*C; i += blockDim.x) sIn[i] = in[i];
    __syncthreads();
    int warp = threadIdx.x >> 5, lane = threadIdx.x & 31;
    int warps = blockDim.x >> 5;
    int f = blockIdx.x*warps + warp;
    if (f >= F) return;
    float a0=0.f,a1=0.f,a2=0.f,a3=0.f;
    const float4* Wr = (const float4*)(W + (size_t)f*C);
    int C4 = C >> 2;
    for (int c4 = lane; c4 < C4; c4 += 32) {
        float4 w = Wr[c4];
        int c = c4 << 2;
        a0 += w.x*sIn[c]       + w.y*sIn[c+1]       + w.z*sIn[c+2]       + w.w*sIn[c+3];
        a1 += w.x*sIn[C+c]     + w.y*sIn[C+c+1]     + w.z*sIn[C+c+2]     + w.w*sIn[C+c+3];
        a2 += w.x*sIn[2*C+c]   + w.y*sIn[2*C+c+1]   + w.z*sIn[2*C+c+2]   + w.w*sIn[2*C+c+3];
        a3 += w.x*sIn[3*C+c]   + w.y*sIn[3*C+c+1]   + w.z*sIn[3*C+c+2]   + w.w*sIn[3*C+c+3];
    }
    #pragma unroll
    for (int s=16;s>0;s>>=1){
        a0 += __shfl_down_sync(0xffffffffu, a0, s);
        a1 += __shfl_down_sync(0xffffffffu, a1, s);
        a2 += __shfl_down_sync(0xffffffffu, a2, s);
        a3 += __shfl_down_sync(0xffffffffu, a3, s);
    }
    if (lane == 0){
        if (mode == 2){
            float m = 0.25f*(a0+a1+a2+a3);
            float d0=a0-m, d1=a1-m, d2=a2-m, d3=a3-m;
            float var = 0.25f*(d0*d0+d1*d1+d2*d2+d3*d3);
            float rs = rsqrtf(var + 1e-5f);
            float v;
            v=d0*rs; out[0*F+f] = (v>0.f)?v:0.2f*v;
            v=d1*rs; out[1*F+f] = (v>0.f)?v:0.2f*v;
            v=d2*rs; out[2*F+f] = (v>0.f)?v:0.2f*v;
            v=d3*rs; out[3*F+f] = (v>0.f)?v:0.2f*v;
        } else {
            float bb = bias ? bias[f] : 0.f;
            a0+=bb; a1+=bb; a2+=bb; a3+=bb;
            if (mode == 1){ a0=fmaxf(a0,0.f); a1=fmaxf(a1,0.f); a2=fmaxf(a2,0.f); a3=fmaxf(a3,0.f); }
            out[0*F+f]=a0; out[1*F+f]=a1; out[2*F+f]=a2; out[3*F+f]=a3;
        }
    }
}

__global__ void k_pc2xyz(const float* __restrict__ w, const float* __restrict__ bias){
    __shared__ float sw[192];
    int b = blockIdx.x, n = threadIdx.x;
    for (int i = threadIdx.x; i < 192; i += 128) sw[i] = w[i];
    __syncthreads();
    float a0 = bias[0], a1 = bias[1], a2 = bias[2];
    for (int c=0;c<64;c++){
        float f = g_pc2f[b*8192 + c*128 + n];
        a0 += sw[c]*f; a1 += sw[64+c]*f; a2 += sw[128+c]*f;
    }
    g_pc2xyz[b*384 + 0*128 + n] = a0;
    g_pc2xyz[b*384 + 1*128 + n] = a1;
    g_pc2xyz[b*384 + 2*128 + n] = a2;
}

__global__ void k_pc3tmp(const float* __restrict__ w1, const float* __restrict__ b1){
    int b = blockIdx.x, o = blockIdx.y, n = threadIdx.x;
    float acc = b1[o];
    const float* w = w1 + o*128;
    const float* f = g_pc3f + b*65536 + n;
    for (int c=0;c<128;c++) acc += w[c]*f[c*512];
    g_pc3tmp[(b*64+o)*512+n] = fmaxf(acc, 0.f);
}

__global__ void k_pc3xyz(const float* __restrict__ w2, const float* __restrict__ b2){
    __shared__ float sw[192];
    int b = blockIdx.x, n = threadIdx.x;
    for (int i = threadIdx.x; i < 192; i += 512) sw[i] = w2[i];
    __syncthreads();
    float a0 = b2[0], a1 = b2[1], a2 = b2[2];
    for (int o=0;o<64;o++){
        float t = g_pc3tmp[(b*64+o)*512+n];
        a0 += sw[o]*t; a1 += sw[64+o]*t; a2 += sw[128+o]*t;
    }
    g_pc3xyz[b*1536 + 0*512 + n] = a0;
    g_pc3xyz[b*1536 + 1*512 + n] = a1;
    g_pc3xyz[b*1536 + 2*512 + n] = a2;
}

__global__ void k_expand1(float* __restrict__ out){
    __shared__ float px[64], py[64], pz[64], pxx[64];
    int b = blockIdx.x, i = threadIdx.x;
    float vx = g_pc1[b*192 + 0*64 + i];
    float vy = g_pc1[b*192 + 1*64 + i];
    float vz = g_pc1[b*192 + 2*64 + i];
    px[i]=vx; py[i]=vy; pz[i]=vz; pxx[i]=vx*vx+vy*vy+vz*vz;
    __syncthreads();
    float cx=px[i], cy=py[i], cz=pz[i], cxx=pxx[i];
    float best=-1e30f; int bj=0;
    for (int j=0;j<64;j++){
        float pd = 2.f*(cx*px[j]+cy*py[j]+cz*pz[j]) - cxx - pxx[j];
        if (pd > best){ best=pd; bj=j; }
    }
    out[(b*64+i)*3+0]=cx; out[(b*64+i)*3+1]=cy; out[(b*64+i)*3+2]=cz;
    float* mid = out + 768;
    const float* p2 = g_pc2xyz + b*384;
    int n0 = 2*i, n1 = 2*i+1;
    float nx=px[bj], ny=py[bj], nz=pz[bj];
    mid[(b*128+n0)*3+0] = (2.f*cx - nx) + p2[0*128+n0];
    mid[(b*128+n0)*3+1] = (2.f*cy - ny) + p2[1*128+n0];
    mid[(b*128+n0)*3+2] = (2.f*cz - nz) + p2[2*128+n0];
    mid[(b*128+n1)*3+0] = cx + p2[0*128+n1];
    mid[(b*128+n1)*3+1] = cy + p2[1*128+n1];
    mid[(b*128+n1)*3+2] = cz + p2[2*128+n1];
}

__global__ void k_expand2(float* __restrict__ out){
    __shared__ float px[128], py[128], pz[128], pxx[128];
    int b = blockIdx.x, i = threadIdx.x;
    float vx = g_pc2xyz[b*384 + 0*128 + i];
    float vy = g_pc2xyz[b*384 + 1*128 + i];
    float vz = g_pc2xyz[b*384 + 2*128 + i];
    px[i]=vx; py[i]=vy; pz[i]=vz; pxx[i]=vx*vx+vy*vy+vz*vz;
    __syncthreads();
    float cx=px[i], cy=py[i], cz=pz[i], cxx=pxx[i];
    float pd0=-1e30f,pd1=-1e30f,pd2=-1e30f; int j0=0,j1=0,j2=0;
    for (int j=0;j<128;j++){
        float pd = 2.f*(cx*px[j]+cy*py[j]+cz*pz[j]) - cxx - pxx[j];
        if (pd > pd2){
            if (pd > pd1){
                pd2=pd1; j2=j1;
                if (pd > pd0){ pd1=pd0; j1=j0; pd0=pd; j0=j; }
                else { pd1=pd; j1=j; }
            } else { pd2=pd; j2=j; }
        }
    }
    float* hi = out + 2304;
    const float* p3 = g_pc3xyz + b*1536;
    int jn[3] = {j0, j1, j2};
    #pragma unroll
    for (int m=0;m<3;m++){
        int n = 4*i+m, j = jn[m];
        hi[(b*512+n)*3+0] = (2.f*cx - px[j]) + p3[0*512+n];
        hi[(b*512+n)*3+1] = (2.f*cy - py[j]) + p3[1*512+n];
        hi[(b*512+n)*3+2] = (2.f*cz - pz[j]) + p3[2*512+n];
    }
    int n = 4*i+3;
    hi[(b*512+n)*3+0] = cx + p3[0*512+n];
    hi[(b*512+n)*3+1] = cy + p3[1*512+n];
    hi[(b*512+n)*3+2] = cz + p3[2*512+n];
}

// ---------------- host ----------------

static const double INV_EDGE = 1.0/131072.0;
static const double INV_PW   = 1.0/8192.0;

#define WO2 512
#define WO3 2560
#define WO4 10752
#define SO21 0
#define SO31 8192
#define SO5  40960

extern "C" void kernel_launch(void* const* d_in, const int* in_sizes, int n_in,
                              void* d_out, int out_size) {
    const float* x         = (const float*)d_in[0];
    const float* conv1_w   = (const float*)d_in[1];
    const float* conv2_w   = (const float*)d_in[2];
    const float* conv2_1_w = (const float*)d_in[3];
    const float* conv3_w   = (const float*)d_in[4];
    const float* conv3_1_w = (const float*)d_in[5];
    const float* conv4_w   = (const float*)d_in[6];
    const float* conv5_w   = (const float*)d_in[7];
    const float* linear1_w = (const float*)d_in[8];
    const float* fc1_w = (const float*)d_in[9];   const float* fc1_b = (const float*)d_in[10];
    const float* fc2_w = (const float*)d_in[11];  const float* fc2_b = (const float*)d_in[12];
    const float* fc3_w = (const float*)d_in[13];  const float* fc3_b = (const float*)d_in[14];
    const float* fc1_1_w = (const float*)d_in[15]; const float* fc1_1_b = (const float*)d_in[16];
    const float* fc2_1_w = (const float*)d_in[17]; const float* fc2_1_b = (const float*)d_in[18];
    const float* fc3_1_w = (const float*)d_in[19]; const float* fc3_1_b = (const float*)d_in[20];
    const float* gc11_w = (const float*)d_in[21];  const float* gc11_b = (const float*)d_in[22];
    const float* gc12_w = (const float*)d_in[23];  const float* gc12_b = (const float*)d_in[24];
    const float* gc21_w = (const float*)d_in[25];  const float* gc21_b = (const float*)d_in[26];
    float* out = (float*)d_out;

    // 0. weight splits
    k_wsplit_dual<<<(64*32+255)/256, 256>>>(conv2_w, WO2, 64, 64, 32);
    k_wsplit_dual<<<(128*64+255)/256, 256>>>(conv3_w, WO3, 128, 128, 64);
    k_wsplit_dual<<<(512*128+255)/256, 256>>>(conv4_w, WO4, 512, 256, 128);
    k_wsplit_stats<<<(128*64+255)/256, 256>>>(conv2_1_w, SO21, 128, 128, 64);
    k_wsplit_stats<<<(256*128+255)/256, 256>>>(conv3_1_w, SO31, 256, 256, 128);
    k_wsplit_stats<<<(1024*384+255)/256, 256>>>(conv5_w, SO5, 1024, 768, 384);

    // 1. fused transpose+pairs, then KNN (8 threads/point, three-stage bitonic merge)
    k_xt<<<(8*COLS)/256, 256>>>(x);
    k_knn<<<dim3(NB, 64), 256>>>();

    // 2. conv1 (fused fp32 gemm+gather): C=3 -> O=64 -> X pairs [0,32)
    k_zero<<<1, 256>>>(64);
    k_gather1<<<dim3(32, NB), 256>>>(conv1_w);
    k_finalize<<<1, 256>>>(64, INV_EDGE);
    k_bn_act<<<(32*COLS)/256, 256>>>(0, 0, 0, 64);

    // 3. conv2 (edge): C=64 -> O=64 -> X pairs [32,64)
    k_zero<<<1, 256>>>(64);
    k_gemm_dual<<<dim3(COLS/128, 1), 256>>>(1, WO2, 64, 32);
    k_gather2<<<dim3(32, NB), 256>>>();
    k_finalize<<<1, 256>>>(64, INV_EDGE);
    k_bn_act<<<(32*COLS)/256, 256>>>(0, 0, 32, 64);

    // 4. conv2_1: K=128 -> O=128 -> H pairs
    k_zero<<<1, 256>>>(128);
    k_gemm_stats<<<dim3(COLS/128, 2), 256>>>(1, SO21, 128, 64);
    k_finalize<<<1, 256>>>(128, INV_PW);
    k_bn_act<<<(64*COLS)/256, 256>>>(1, 1, 0, 128);

    // 5. conv3 (edge): C=128 (h) -> O=128 -> X pairs [64,128)
    k_zero<<<1, 256>>>(128);
    k_gemm_dual<<<dim3(COLS/128, 2), 256>>>(2, WO3, 128, 64);
    k_gather2<<<dim3(64, NB), 256>>>();
    k_finalize<<<1, 256>>>(128, INV_EDGE);
    k_bn_act<<<(64*COLS)/256, 256>>>(0, 0, 64, 128);

    // 6. conv3_1: K=256 -> O=256 -> H pairs
    k_zero<<<1, 256>>>(256);
    k_gemm_stats<<<dim3(COLS/128, 4), 256>>>(1, SO31, 256, 128);
    k_finalize<<<1, 256>>>(256, INV_PW);
    k_bn_act<<<(128*COLS)/256, 256>>>(1, 1, 0, 256);

    // 7. conv4 (edge): C=256 (h) -> O=512 -> X pairs [128,384)
    k_zero<<<2, 256>>>(512);
    k_gemm_dual<<<dim3(COLS/128, 8), 256>>>(2, WO4, 256, 128);
    k_gather2<<<dim3(256, NB), 256>>>();
    k_finalize<<<2, 256>>>(512, INV_EDGE);
    k_bn_act<<<(256*COLS)/256, 256>>>(0, 0, 128, 512);

    // 8. conv5: K=768 -> O=1024 -> H pairs
    k_zero<<<4, 256>>>(1024);
    k_gemm_stats<<<dim3(COLS/128, 16), 256>>>(1, SO5, 768, 384);
    k_finalize<<<4, 256>>>(1024, INV_PW);
    k_bn_act<<<(512*COLS)/256, 256>>>(1, 1, 0, 1024);

    // 9. global pooling from pairs
    k_pool<<<dim3(512, NB), 256>>>();

    // 10-12. fc chain + heads
    k_fc<<<2048/8, 256, 4*2048*4>>>(linear1_w, nullptr, 0, 1, 2048, 2048, 2);
    k_fc<<<1024/8, 256, 4*2048*4>>>(fc1_w, fc1_b, 1, 2, 1024, 2048, 1);
    k_fc<<<512/8, 256, 4*1024*4>>>(fc2_w, fc2_b, 2, 3, 512, 1024, 1);
    k_fc<<<256/8, 256, 4*512*4>>>(fc3_w, fc3_b, 3, 4, 256, 512, 1);
    k_fc<<<192/8, 256, 4*256*4>>>(fc3_1_w, fc3_1_b, 4, 5, 192, 256, 0);
    k_fc<<<8192/32, 1024, 4*512*4>>>(fc2_1_w, fc2_1_b, 3, 6, 8192, 512, 1);
    k_fc<<<65536/32, 1024, 4*1024*4>>>(fc1_1_w, fc1_1_b, 2, 7, 65536, 1024, 1);

    // 13. small convs
    k_pc2xyz<<<NB, 128>>>(gc21_w, gc21_b);
    k_pc3tmp<<<dim3(NB, 64), 512>>>(gc11_w, gc11_b);
    k_pc3xyz<<<NB, 512>>>(gc12_w, gc12_b);

    // 14. mirror expansions + final outputs
    k_expand1<<<NB, 64>>>(out);
    k_expand2<<<NB, 128>>>(out);
}